// round 3
// baseline (speedup 1.0000x reference)
#include <cuda_runtime.h>
#include <math.h>
#include <stdint.h>

#define BEPS 1e-5f
#define NB 4096

// ---------------- scratch (allocation-free) ----------------
__device__ float h2_g[NB * 784];
__device__ float h3T_g[(size_t)NB * 25 * 256];       // [(b*25+pos)][d]
__device__ float xp_g[(size_t)NB * 25 * 512];        // [(b*25+pos)][p]
__device__ float w_g[NB * 512];
__device__ float z_g[NB * 256];
__device__ float up_g[(size_t)NB * 6400];
__device__ float protoT_g[256 * 512];                // [d][p]
__device__ float pp_g[512];                          // sum_d proto^2
__device__ float w3t_g[256 * 144];                   // [(c*9+tap)][oc]
__device__ float wd1t_g[256 * 144];                  // [c][tap*16+o]

// ---------------- packed fp32x2 helpers (sm_100+) ----------------
static __device__ __forceinline__ unsigned long long ffma2(
    unsigned long long a, unsigned long long b, unsigned long long c) {
    unsigned long long d;
    asm("fma.rn.f32x2 %0, %1, %2, %3;" : "=l"(d) : "l"(a), "l"(b), "l"(c));
    return d;
}
static __device__ __forceinline__ unsigned long long pack2(float x, float y) {
    unsigned long long r;
    asm("mov.b64 %0, {%1, %2};" : "=l"(r) : "f"(x), "f"(y));
    return r;
}
static __device__ __forceinline__ float2 unpack2(unsigned long long v) {
    float2 r;
    asm("mov.b64 {%0, %1}, %2;" : "=f"(r.x), "=f"(r.y) : "l"(v));
    return r;
}

// ---------------- tf32 helpers ----------------
static __device__ __forceinline__ void cvt_hilo(float x, uint32_t& hi, uint32_t& lo) {
    uint32_t h;
    asm("cvt.rna.tf32.f32 %0, %1;" : "=r"(h) : "f"(x));
    float hf = __uint_as_float(h);
    float l = x - hf;
    asm("cvt.rna.tf32.f32 %0, %1;" : "=r"(lo) : "f"(l));
    hi = h;
}
static __device__ __forceinline__ void mma_tf32(float* c, const uint32_t* a, const uint32_t* b) {
    asm volatile(
        "mma.sync.aligned.m16n8k8.row.col.f32.tf32.tf32.f32 "
        "{%0,%1,%2,%3}, {%4,%5,%6,%7}, {%8,%9}, {%0,%1,%2,%3};"
        : "+f"(c[0]), "+f"(c[1]), "+f"(c[2]), "+f"(c[3])
        : "r"(a[0]), "r"(a[1]), "r"(a[2]), "r"(a[3]), "r"(b[0]), "r"(b[1]));
}

// ---------------------------------------------------------------------------
// prep: weight transposes + proto norms
// ---------------------------------------------------------------------------
__global__ void prep_kernel(const float* __restrict__ proto,
                            const float* __restrict__ w3,
                            const float* __restrict__ wd1)
{
    int stride = gridDim.x * blockDim.x;
    int tid = blockIdx.x * blockDim.x + threadIdx.x;
    for (int i = tid; i < 512 * 256; i += stride) {
        int d = i >> 9, p = i & 511;
        protoT_g[i] = proto[p * 256 + d];
    }
    for (int p = tid; p < 512; p += stride) {
        float s = 0.f;
        for (int d = 0; d < 256; d++) {
            float v = proto[p * 256 + d];
            s += v * v;
        }
        pp_g[p] = s;
    }
    for (int i = tid; i < 256 * 144; i += stride) {
        int o = i & 255, ct = i >> 8;
        int c = ct / 9, tap = ct - c * 9;
        w3t_g[i] = w3[o * 144 + c * 9 + tap];
    }
    for (int i = tid; i < 256 * 144; i += stride) {
        int o = i & 15, ct = i >> 4;
        int c = ct / 9, tap = ct - c * 9;
        wd1t_g[c * 144 + tap * 16 + o] = wd1[c * 144 + o * 9 + tap];
    }
}

// ---------------------------------------------------------------------------
// enc12: conv1 + conv2, one block per image
// ---------------------------------------------------------------------------
__global__ __launch_bounds__(128) void enc12_kernel(
    const float* __restrict__ x,
    const float* __restrict__ w1, const float* __restrict__ b1,
    const float* __restrict__ w2, const float* __restrict__ b2,
    const float* __restrict__ g2, const float* __restrict__ bt2)
{
    __shared__ float xs[784];
    __shared__ float h1s[8 * 196];
    const int b = blockIdx.x;
    const int t = threadIdx.x;

    const float* xb = x + b * 784;
    for (int i = t; i < 784; i += 128) xs[i] = xb[i];
    __syncthreads();

    for (int idx = t; idx < 1568; idx += 128) {
        int o = idx / 196, r = idx % 196, i = r / 14, j = r % 14;
        float acc = b1[o];
        #pragma unroll
        for (int ky = 0; ky < 3; ky++) {
            int y = 2 * i - 1 + ky;
            if ((unsigned)y >= 28u) continue;
            #pragma unroll
            for (int kx = 0; kx < 3; kx++) {
                int xx = 2 * j - 1 + kx;
                if ((unsigned)xx >= 28u) continue;
                acc += xs[y * 28 + xx] * w1[o * 9 + ky * 3 + kx];
            }
        }
        h1s[idx] = fmaxf(acc, 0.f);
    }
    __syncthreads();

    const float rs = rsqrtf(1.f + BEPS);
    for (int idx = t; idx < 784; idx += 128) {
        int o = idx / 49, r = idx % 49, i = r / 7, j = r % 7;
        float acc = 0.f;
        for (int c = 0; c < 8; c++) {
            #pragma unroll
            for (int ky = 0; ky < 3; ky++) {
                int y = 2 * i - 1 + ky;
                if ((unsigned)y >= 14u) continue;
                #pragma unroll
                for (int kx = 0; kx < 3; kx++) {
                    int xx = 2 * j - 1 + kx;
                    if ((unsigned)xx >= 14u) continue;
                    acc += h1s[c * 196 + y * 14 + xx] * w2[((o * 8 + c) * 3 + ky) * 3 + kx];
                }
            }
        }
        float s = g2[o] * rs;
        h2_g[b * 784 + idx] = fmaxf((acc + b2[o]) * s + bt2[o], 0.f);
    }
}

// ---------------------------------------------------------------------------
// conv3: 16->256 k3 s1 p0, 7->5; writes h3 transposed [(b*25+pos)][d]
// ---------------------------------------------------------------------------
__global__ __launch_bounds__(256, 2) void conv3_kernel(const float* __restrict__ b3)
{
    __shared__ float h2s[784];
    const int b = blockIdx.x;
    const int t = threadIdx.x;

    for (int i = t; i < 784; i += 256) h2s[i] = h2_g[b * 784 + i];
    __syncthreads();

    float acc[25];
    #pragma unroll
    for (int p = 0; p < 25; p++) acc[p] = 0.f;

    for (int c = 0; c < 16; c++) {
        float w[9];
        #pragma unroll
        for (int tap = 0; tap < 9; tap++) w[tap] = w3t_g[(c * 9 + tap) * 256 + t];
        float h[49];
        #pragma unroll
        for (int i = 0; i < 49; i++) h[i] = h2s[c * 49 + i];
        #pragma unroll
        for (int ky = 0; ky < 3; ky++)
            #pragma unroll
            for (int kx = 0; kx < 3; kx++) {
                float wv = w[ky * 3 + kx];
                #pragma unroll
                for (int i = 0; i < 5; i++)
                    #pragma unroll
                    for (int j = 0; j < 5; j++)
                        acc[i * 5 + j] += wv * h[(i + ky) * 7 + (j + kx)];
            }
    }
    float bb = b3[t];
    #pragma unroll
    for (int p = 0; p < 25; p++)
        h3T_g[((size_t)b * 25 + p) * 256 + t] = fmaxf(acc[p] + bb, 0.f);
}

// ---------------------------------------------------------------------------
// xp GEMM: C[102400x512] = h3T[102400x256] * protoT[256x512], 3xTF32.
// 64x64 tile, 256 threads (8 warps: wm in {0,1}, wn in {0..3}), k-chunk 32.
// ---------------------------------------------------------------------------
__global__ __launch_bounds__(256) void xp_gemm_kernel()
{
    __shared__ uint32_t Ah[64 * 36], Al[64 * 36];   // [m][k] stride 36
    __shared__ uint32_t Bh[32 * 68], Bl[32 * 68];   // [k][n] stride 68

    const int t = threadIdx.x;
    const int lane = t & 31, wid = t >> 5;
    const int wm = wid & 1, wn = wid >> 1;
    const int bm = blockIdx.y * 64;
    const int bn = blockIdx.x * 64;

    float acc[2][2][4];
    #pragma unroll
    for (int i = 0; i < 2; i++)
        #pragma unroll
        for (int j = 0; j < 2; j++)
            #pragma unroll
            for (int k = 0; k < 4; k++) acc[i][j][k] = 0.f;

    const int ar = t >> 2, ac8 = (t & 3) * 8;       // A loader: row, col-base
    const int bk = t >> 3, bn8 = (t & 7) * 8;       // B loader

    for (int k0 = 0; k0 < 256; k0 += 32) {
        // load + convert A (64x32)
        {
            const float* src = &h3T_g[(size_t)(bm + ar) * 256 + k0 + ac8];
            float4 v0 = *(const float4*)src;
            float4 v1 = *(const float4*)(src + 4);
            float vs[8] = {v0.x, v0.y, v0.z, v0.w, v1.x, v1.y, v1.z, v1.w};
            #pragma unroll
            for (int j = 0; j < 8; j++) {
                uint32_t hi, lo;
                cvt_hilo(vs[j], hi, lo);
                Ah[ar * 36 + ac8 + j] = hi;
                Al[ar * 36 + ac8 + j] = lo;
            }
        }
        // load + convert B (32x64)
        {
            const float* src = &protoT_g[(size_t)(k0 + bk) * 512 + bn + bn8];
            float4 v0 = *(const float4*)src;
            float4 v1 = *(const float4*)(src + 4);
            float vs[8] = {v0.x, v0.y, v0.z, v0.w, v1.x, v1.y, v1.z, v1.w};
            #pragma unroll
            for (int j = 0; j < 8; j++) {
                uint32_t hi, lo;
                cvt_hilo(vs[j], hi, lo);
                Bh[bk * 68 + bn8 + j] = hi;
                Bl[bk * 68 + bn8 + j] = lo;
            }
        }
        __syncthreads();

        #pragma unroll
        for (int ks = 0; ks < 4; ks++) {
            const int k = ks * 8;
            uint32_t AHf[2][4], ALf[2][4], BHf[2][2], BLf[2][2];
            #pragma unroll
            for (int ms = 0; ms < 2; ms++) {
                int mb = wm * 32 + ms * 16 + (lane >> 2);
                int col = k + (lane & 3);
                AHf[ms][0] = Ah[mb * 36 + col];
                AHf[ms][1] = Ah[(mb + 8) * 36 + col];
                AHf[ms][2] = Ah[mb * 36 + col + 4];
                AHf[ms][3] = Ah[(mb + 8) * 36 + col + 4];
                ALf[ms][0] = Al[mb * 36 + col];
                ALf[ms][1] = Al[(mb + 8) * 36 + col];
                ALf[ms][2] = Al[mb * 36 + col + 4];
                ALf[ms][3] = Al[(mb + 8) * 36 + col + 4];
            }
            #pragma unroll
            for (int ns = 0; ns < 2; ns++) {
                int nb = wn * 16 + ns * 8 + (lane >> 2);
                int row = k + (lane & 3);
                BHf[ns][0] = Bh[row * 68 + nb];
                BHf[ns][1] = Bh[(row + 4) * 68 + nb];
                BLf[ns][0] = Bl[row * 68 + nb];
                BLf[ns][1] = Bl[(row + 4) * 68 + nb];
            }
            #pragma unroll
            for (int ms = 0; ms < 2; ms++)
                #pragma unroll
                for (int ns = 0; ns < 2; ns++) {
                    mma_tf32(acc[ms][ns], AHf[ms], BHf[ns]);
                    mma_tf32(acc[ms][ns], AHf[ms], BLf[ns]);
                    mma_tf32(acc[ms][ns], ALf[ms], BHf[ns]);
                }
        }
        __syncthreads();
    }

    #pragma unroll
    for (int ms = 0; ms < 2; ms++)
        #pragma unroll
        for (int ns = 0; ns < 2; ns++) {
            int row0 = bm + wm * 32 + ms * 16 + (lane >> 2);
            int col0 = bn + wn * 16 + ns * 8 + 2 * (lane & 3);
            *(float2*)&xp_g[(size_t)row0 * 512 + col0] =
                make_float2(acc[ms][ns][0], acc[ms][ns][1]);
            *(float2*)&xp_g[(size_t)(row0 + 8) * 512 + col0] =
                make_float2(acc[ms][ns][2], acc[ms][ns][3]);
        }
}

// ---------------------------------------------------------------------------
// minsoftmax: distances from xp, min over pos, softmax -> w_g, minD out.
// Block = image, 512 threads (one per prototype).
// ---------------------------------------------------------------------------
__global__ __launch_bounds__(512) void minsoftmax_kernel(float* __restrict__ out_minD)
{
    __shared__ float x2s[25];
    __shared__ float red[32];

    const int b = blockIdx.x;
    const int t = threadIdx.x;
    const int lane = t & 31, wid = t >> 5;

    // x2 per position (warps cover pos 0..24)
    for (int pos = wid; pos < 25; pos += 16) {
        const float* row = &h3T_g[((size_t)b * 25 + pos) * 256];
        float s = 0.f;
        #pragma unroll
        for (int j = 0; j < 8; j++) {
            float v = row[lane + 32 * j];
            s += v * v;
        }
        #pragma unroll
        for (int off = 16; off; off >>= 1) s += __shfl_xor_sync(0xffffffffu, s, off);
        if (!lane) x2s[pos] = s;
    }
    __syncthreads();

    const float pp = pp_g[t];
    float m = 3.0e38f;
    #pragma unroll 5
    for (int pos = 0; pos < 25; pos++) {
        float xv = xp_g[((size_t)b * 25 + pos) * 512 + t];
        float d = fmaxf(x2s[pos] - 2.f * xv + pp, 0.f);
        m = fminf(m, d);
    }
    out_minD[(size_t)b * 512 + t] = m;

    // softmax over 512
    float a = -m;
    float v = a;
    #pragma unroll
    for (int off = 16; off; off >>= 1) v = fmaxf(v, __shfl_xor_sync(0xffffffffu, v, off));
    if (!lane) red[wid] = v;
    __syncthreads();
    if (t == 0) {
        float r = red[0];
        for (int i = 1; i < 16; i++) r = fmaxf(r, red[i]);
        red[16] = r;
    }
    __syncthreads();
    float amax = red[16];
    float e = expf(a - amax);
    float sv = e;
    #pragma unroll
    for (int off = 16; off; off >>= 1) sv += __shfl_xor_sync(0xffffffffu, sv, off);
    __syncthreads();
    if (!lane) red[wid] = sv;
    __syncthreads();
    if (t == 0) {
        float r = 0.f;
        for (int i = 0; i < 16; i++) r += red[i];
        red[16] = r;
    }
    __syncthreads();
    w_g[(size_t)b * 512 + t] = e * (1.f / red[16]);
}

// ---------------------------------------------------------------------------
// z GEMM (FFMA f32x2): z[4096x256] = w[4096x512] * proto[512x256]
// ---------------------------------------------------------------------------
__global__ __launch_bounds__(256) void z_gemm_kernel(const float* __restrict__ proto)
{
    __shared__ __align__(16) float As[16][128];
    __shared__ __align__(16) float Bs[16][64];
    const int bn = blockIdx.x * 64;
    const int bm = blockIdx.y * 128;
    const int t = threadIdx.x;
    const int tx = t & 15, ty = t >> 4;

    unsigned long long acc[4][4];
    #pragma unroll
    for (int i = 0; i < 4; i++)
        #pragma unroll
        for (int j = 0; j < 4; j++) acc[i][j] = 0ull;

    for (int k0 = 0; k0 < 512; k0 += 16) {
        #pragma unroll
        for (int s = t; s < 512; s += 256) {
            int r = s >> 2, kq = (s & 3) << 2;
            float4 v = *(const float4*)&w_g[(size_t)(bm + r) * 512 + k0 + kq];
            As[kq + 0][r] = v.x; As[kq + 1][r] = v.y;
            As[kq + 2][r] = v.z; As[kq + 3][r] = v.w;
        }
        {
            int kk = t >> 4, n4 = (t & 15) << 2;
            *(float4*)&Bs[kk][n4] = *(const float4*)&proto[(size_t)(k0 + kk) * 256 + bn + n4];
        }
        __syncthreads();
        #pragma unroll
        for (int kk = 0; kk < 16; kk++) {
            ulonglong2 a01 = *(const ulonglong2*)&As[kk][ty * 8];
            ulonglong2 a23 = *(const ulonglong2*)&As[kk][ty * 8 + 4];
            float4 bv = *(const float4*)&Bs[kk][tx * 4];
            unsigned long long bd0 = pack2(bv.x, bv.x), bd1 = pack2(bv.y, bv.y);
            unsigned long long bd2 = pack2(bv.z, bv.z), bd3 = pack2(bv.w, bv.w);
            acc[0][0] = ffma2(a01.x, bd0, acc[0][0]); acc[0][1] = ffma2(a01.x, bd1, acc[0][1]);
            acc[0][2] = ffma2(a01.x, bd2, acc[0][2]); acc[0][3] = ffma2(a01.x, bd3, acc[0][3]);
            acc[1][0] = ffma2(a01.y, bd0, acc[1][0]); acc[1][1] = ffma2(a01.y, bd1, acc[1][1]);
            acc[1][2] = ffma2(a01.y, bd2, acc[1][2]); acc[1][3] = ffma2(a01.y, bd3, acc[1][3]);
            acc[2][0] = ffma2(a23.x, bd0, acc[2][0]); acc[2][1] = ffma2(a23.x, bd1, acc[2][1]);
            acc[2][2] = ffma2(a23.x, bd2, acc[2][2]); acc[2][3] = ffma2(a23.x, bd3, acc[2][3]);
            acc[3][0] = ffma2(a23.y, bd0, acc[3][0]); acc[3][1] = ffma2(a23.y, bd1, acc[3][1]);
            acc[3][2] = ffma2(a23.y, bd2, acc[3][2]); acc[3][3] = ffma2(a23.y, bd3, acc[3][3]);
        }
        __syncthreads();
    }

    #pragma unroll
    for (int mp = 0; mp < 4; mp++) {
        int m0 = bm + ty * 8 + mp * 2;
        float2 f0 = unpack2(acc[mp][0]), f1 = unpack2(acc[mp][1]);
        float2 f2 = unpack2(acc[mp][2]), f3 = unpack2(acc[mp][3]);
        float4 r0 = make_float4(f0.x, f1.x, f2.x, f3.x);
        float4 r1 = make_float4(f0.y, f1.y, f2.y, f3.y);
        *(float4*)&z_g[(size_t)m0 * 256 + bn + tx * 4] = r0;
        *(float4*)&z_g[(size_t)(m0 + 1) * 256 + bn + tx * 4] = r1;
    }
}

// ---------------------------------------------------------------------------
// up GEMM (3xTF32): up[4096x6400] = relu(BN(z[4096x256] * wup[256x6400]))
// ---------------------------------------------------------------------------
__global__ __launch_bounds__(256) void up_gemm_kernel(
    const float* __restrict__ wup, const float* __restrict__ bup,
    const float* __restrict__ gup, const float* __restrict__ btup)
{
    __shared__ uint32_t Ah[64 * 36], Al[64 * 36];
    __shared__ uint32_t Bh[32 * 68], Bl[32 * 68];

    const int t = threadIdx.x;
    const int lane = t & 31, wid = t >> 5;
    const int wm = wid & 1, wn = wid >> 1;
    const int bm = blockIdx.y * 64;
    const int bn = blockIdx.x * 64;

    float acc[2][2][4];
    #pragma unroll
    for (int i = 0; i < 2; i++)
        #pragma unroll
        for (int j = 0; j < 2; j++)
            #pragma unroll
            for (int k = 0; k < 4; k++) acc[i][j][k] = 0.f;

    const int ar = t >> 2, ac8 = (t & 3) * 8;
    const int bk = t >> 3, bn8 = (t & 7) * 8;

    for (int k0 = 0; k0 < 256; k0 += 32) {
        {
            const float* src = &z_g[(size_t)(bm + ar) * 256 + k0 + ac8];
            float4 v0 = *(const float4*)src;
            float4 v1 = *(const float4*)(src + 4);
            float vs[8] = {v0.x, v0.y, v0.z, v0.w, v1.x, v1.y, v1.z, v1.w};
            #pragma unroll
            for (int j = 0; j < 8; j++) {
                uint32_t hi, lo;
                cvt_hilo(vs[j], hi, lo);
                Ah[ar * 36 + ac8 + j] = hi;
                Al[ar * 36 + ac8 + j] = lo;
            }
        }
        {
            const float* src = &wup[(size_t)(k0 + bk) * 6400 + bn + bn8];
            float4 v0 = *(const float4*)src;
            float4 v1 = *(const float4*)(src + 4);
            float vs[8] = {v0.x, v0.y, v0.z, v0.w, v1.x, v1.y, v1.z, v1.w};
            #pragma unroll
            for (int j = 0; j < 8; j++) {
                uint32_t hi, lo;
                cvt_hilo(vs[j], hi, lo);
                Bh[bk * 68 + bn8 + j] = hi;
                Bl[bk * 68 + bn8 + j] = lo;
            }
        }
        __syncthreads();

        #pragma unroll
        for (int ks = 0; ks < 4; ks++) {
            const int k = ks * 8;
            uint32_t AHf[2][4], ALf[2][4], BHf[2][2], BLf[2][2];
            #pragma unroll
            for (int ms = 0; ms < 2; ms++) {
                int mb = wm * 32 + ms * 16 + (lane >> 2);
                int col = k + (lane & 3);
                AHf[ms][0] = Ah[mb * 36 + col];
                AHf[ms][1] = Ah[(mb + 8) * 36 + col];
                AHf[ms][2] = Ah[mb * 36 + col + 4];
                AHf[ms][3] = Ah[(mb + 8) * 36 + col + 4];
                ALf[ms][0] = Al[mb * 36 + col];
                ALf[ms][1] = Al[(mb + 8) * 36 + col];
                ALf[ms][2] = Al[mb * 36 + col + 4];
                ALf[ms][3] = Al[(mb + 8) * 36 + col + 4];
            }
            #pragma unroll
            for (int ns = 0; ns < 2; ns++) {
                int nb = wn * 16 + ns * 8 + (lane >> 2);
                int row = k + (lane & 3);
                BHf[ns][0] = Bh[row * 68 + nb];
                BHf[ns][1] = Bh[(row + 4) * 68 + nb];
                BLf[ns][0] = Bl[row * 68 + nb];
                BLf[ns][1] = Bl[(row + 4) * 68 + nb];
            }
            #pragma unroll
            for (int ms = 0; ms < 2; ms++)
                #pragma unroll
                for (int ns = 0; ns < 2; ns++) {
                    mma_tf32(acc[ms][ns], AHf[ms], BHf[ns]);
                    mma_tf32(acc[ms][ns], AHf[ms], BLf[ns]);
                    mma_tf32(acc[ms][ns], ALf[ms], BHf[ns]);
                }
        }
        __syncthreads();
    }

    const float rsc = rsqrtf(1.f + BEPS);
    #pragma unroll
    for (int ms = 0; ms < 2; ms++)
        #pragma unroll
        for (int ns = 0; ns < 2; ns++) {
            int row0 = bm + wm * 32 + ms * 16 + (lane >> 2);
            int col0 = bn + wn * 16 + ns * 8 + 2 * (lane & 3);
            int o0 = col0 / 25, o1 = (col0 + 1) / 25;
            float s0 = gup[o0] * rsc, s1 = gup[o1] * rsc;
            float bi0 = bup[o0] * s0 + btup[o0];
            float bi1 = bup[o1] * s1 + btup[o1];
            up_g[(size_t)row0 * 6400 + col0]     = fmaxf(acc[ms][ns][0] * s0 + bi0, 0.f);
            up_g[(size_t)row0 * 6400 + col0 + 1] = fmaxf(acc[ms][ns][1] * s1 + bi1, 0.f);
            up_g[(size_t)(row0 + 8) * 6400 + col0]     = fmaxf(acc[ms][ns][2] * s0 + bi0, 0.f);
            up_g[(size_t)(row0 + 8) * 6400 + col0 + 1] = fmaxf(acc[ms][ns][3] * s1 + bi1, 0.f);
        }
}

// ---------------------------------------------------------------------------
// dec: transposed convs. 4 images per block, 256 threads.
// ---------------------------------------------------------------------------
__global__ __launch_bounds__(256) void dec_kernel(
    const float* __restrict__ bd1,
    const float* __restrict__ gd1, const float* __restrict__ btd1,
    const float* __restrict__ wd2, const float* __restrict__ bd2,
    const float* __restrict__ gd2, const float* __restrict__ btd2,
    const float* __restrict__ wd3, const float* __restrict__ bd3,
    float* __restrict__ out)
{
    extern __shared__ float sm[];
    float* ups  = sm;                 // 25600
    float* wts  = ups + 25600;        // 4608
    float* d1s  = wts + 4608;         // 3136
    float* d2s  = d1s + 3136;         // 6272
    float* wd2s = d2s + 6272;         // 1152
    float* wd3s = wd2s + 1152;        // 72

    const int t = threadIdx.x;
    const int b0 = blockIdx.x * 4;
    const float rs = rsqrtf(1.f + BEPS);

    for (int i = t; i < 25600; i += 256) ups[i] = up_g[(size_t)b0 * 6400 + i];
    for (int i = t; i < 1152; i += 256) wd2s[i] = wd2[i];
    if (t < 72) wd3s[t] = wd3[t];

    const int pos = t % 49;
    const int og = t / 49;
    const int oi = pos / 7, oj = pos % 7;
    const int y0 = max(oi - 2, 0), y1 = min(oi, 4);
    const int x0 = max(oj - 2, 0), x1 = min(oj, 4);

    float acc[4][4];
    #pragma unroll
    for (int a = 0; a < 4; a++)
        #pragma unroll
        for (int o = 0; o < 4; o++) acc[a][o] = 0.f;

    for (int c0 = 0; c0 < 256; c0 += 32) {
        __syncthreads();
        for (int i = t; i < 4608; i += 256) wts[i] = wd1t_g[c0 * 144 + i];
        __syncthreads();
        if (t < 196) {
            for (int c = 0; c < 32; c++) {
                int cb = (c0 + c) * 25;
                const float* wb = &wts[c * 144];
                for (int y = y0; y <= y1; y++) {
                    int ki = oi - y;
                    for (int xx = x0; xx <= x1; xx++) {
                        int kj = oj - xx;
                        float4 w4 = *(const float4*)&wb[(ki * 3 + kj) * 16 + og * 4];
                        float u0 = ups[0 * 6400 + cb + y * 5 + xx];
                        float u1 = ups[1 * 6400 + cb + y * 5 + xx];
                        float u2 = ups[2 * 6400 + cb + y * 5 + xx];
                        float u3 = ups[3 * 6400 + cb + y * 5 + xx];
                        acc[0][0] += u0 * w4.x; acc[0][1] += u0 * w4.y;
                        acc[0][2] += u0 * w4.z; acc[0][3] += u0 * w4.w;
                        acc[1][0] += u1 * w4.x; acc[1][1] += u1 * w4.y;
                        acc[1][2] += u1 * w4.z; acc[1][3] += u1 * w4.w;
                        acc[2][0] += u2 * w4.x; acc[2][1] += u2 * w4.y;
                        acc[2][2] += u2 * w4.z; acc[2][3] += u2 * w4.w;
                        acc[3][0] += u3 * w4.x; acc[3][1] += u3 * w4.y;
                        acc[3][2] += u3 * w4.z; acc[3][3] += u3 * w4.w;
                    }
                }
            }
        }
    }
    if (t < 196) {
        #pragma unroll
        for (int oo = 0; oo < 4; oo++) {
            int o = og * 4 + oo;
            float s = gd1[o] * rs;
            float bias = bd1[o] * s + btd1[o];
            #pragma unroll
            for (int a = 0; a < 4; a++)
                d1s[a * 784 + o * 49 + pos] = fmaxf(acc[a][oo] * s + bias, 0.f);
        }
    }
    __syncthreads();

    if (t < 196) {
        float acc2[4][8];
        #pragma unroll
        for (int a = 0; a < 4; a++)
            #pragma unroll
            for (int o = 0; o < 8; o++) acc2[a][o] = 0.f;
        int i = t / 14, j = t % 14;
        int ylo = i / 2, yhi = min((i + 1) / 2, 6);
        int xlo = j / 2, xhi = min((j + 1) / 2, 6);
        for (int c = 0; c < 16; c++) {
            for (int y = ylo; y <= yhi; y++) {
                int ki = i - 2 * y + 1;
                for (int xx = xlo; xx <= xhi; xx++) {
                    int kj = j - 2 * xx + 1;
                    float u0 = d1s[0 * 784 + c * 49 + y * 7 + xx];
                    float u1 = d1s[1 * 784 + c * 49 + y * 7 + xx];
                    float u2 = d1s[2 * 784 + c * 49 + y * 7 + xx];
                    float u3 = d1s[3 * 784 + c * 49 + y * 7 + xx];
                    #pragma unroll
                    for (int o = 0; o < 8; o++) {
                        float wv = wd2s[((c * 8 + o) * 3 + ki) * 3 + kj];
                        acc2[0][o] += u0 * wv;
                        acc2[1][o] += u1 * wv;
                        acc2[2][o] += u2 * wv;
                        acc2[3][o] += u3 * wv;
                    }
                }
            }
        }
        #pragma unroll
        for (int o = 0; o < 8; o++) {
            float s = gd2[o] * rs;
            float bias = bd2[o] * s + btd2[o];
            #pragma unroll
            for (int a = 0; a < 4; a++)
                d2s[a * 1568 + o * 196 + t] = fmaxf(acc2[a][o] * s + bias, 0.f);
        }
    }
    __syncthreads();

    const float bb3 = bd3[0];
    for (int idx = t; idx < 3136; idx += 256) {
        int a = idx / 784, p = idx % 784, i = p / 28, j = p % 28;
        int ylo = i / 2, yhi = min((i + 1) / 2, 13);
        int xlo = j / 2, xhi = min((j + 1) / 2, 13);
        float acc3 = bb3;
        for (int c = 0; c < 8; c++) {
            for (int y = ylo; y <= yhi; y++) {
                int ki = i - 2 * y + 1;
                for (int xx = xlo; xx <= xhi; xx++) {
                    int kj = j - 2 * xx + 1;
                    acc3 += d2s[a * 1568 + c * 196 + y * 14 + xx] * wd3s[c * 9 + ki * 3 + kj];
                }
            }
        }
        out[(size_t)(b0 + a) * 784 + p] = 1.f / (1.f + expf(-acc3));
    }
}

// ---------------------------------------------------------------------------
extern "C" void kernel_launch(void* const* d_in, const int* in_sizes, int n_in,
                              void* d_out, int out_size)
{
    const float* x     = (const float*)d_in[0];
    const float* w1    = (const float*)d_in[1];
    const float* b1    = (const float*)d_in[2];
    const float* w2    = (const float*)d_in[3];
    const float* b2    = (const float*)d_in[4];
    const float* g2    = (const float*)d_in[5];
    const float* bt2   = (const float*)d_in[6];
    const float* w3    = (const float*)d_in[7];
    const float* b3    = (const float*)d_in[8];
    const float* proto = (const float*)d_in[9];
    const float* wup   = (const float*)d_in[10];
    const float* bup   = (const float*)d_in[11];
    const float* gup   = (const float*)d_in[12];
    const float* btup  = (const float*)d_in[13];
    const float* wd1   = (const float*)d_in[14];
    const float* bd1   = (const float*)d_in[15];
    const float* gd1   = (const float*)d_in[16];
    const float* btd1  = (const float*)d_in[17];
    const float* wd2   = (const float*)d_in[18];
    const float* bd2   = (const float*)d_in[19];
    const float* gd2   = (const float*)d_in[20];
    const float* btd2  = (const float*)d_in[21];
    const float* wd3   = (const float*)d_in[22];
    const float* bd3   = (const float*)d_in[23];

    float* out  = (float*)d_out;                 // (4096,1,28,28)
    float* minD = out + (size_t)NB * 784;        // (4096,512)

    prep_kernel<<<128, 256>>>(proto, w3, wd1);
    enc12_kernel<<<NB, 128>>>(x, w1, b1, w2, b2, g2, bt2);
    conv3_kernel<<<NB, 256>>>(b3);

    dim3 gx(512 / 64, (NB * 25) / 64);           // (8, 1600)
    xp_gemm_kernel<<<gx, 256>>>();

    minsoftmax_kernel<<<NB, 512>>>(minD);

    dim3 gz(256 / 64, NB / 128);
    z_gemm_kernel<<<gz, 256>>>(proto);

    dim3 gu(6400 / 64, NB / 64);                 // (100, 64)
    up_gemm_kernel<<<gu, 256>>>(wup, bup, gup, btup);

    size_t smem = (size_t)(25600 + 4608 + 3136 + 6272 + 1152 + 72) * sizeof(float);
    cudaFuncSetAttribute(dec_kernel, cudaFuncAttributeMaxDynamicSharedMemorySize, (int)smem);
    dec_kernel<<<NB / 4, 256, smem>>>(bd1, gd1, btd1,
                                      wd2, bd2, gd2, btd2,
                                      wd3, bd3, out);
}

// round 4
// speedup vs baseline: 1.1941x; 1.1941x over previous
#include <cuda_runtime.h>
#include <math.h>
#include <stdint.h>

#define BEPS 1e-5f
#define NB 4096

// ---------------- scratch (allocation-free) ----------------
__device__ float h2_g[NB * 784];
__device__ float h3T_g[(size_t)NB * 25 * 256];       // [(b*25+pos)][d]
__device__ float xp_g[(size_t)NB * 25 * 512];        // [(b*25+pos)][p]
__device__ float w_g[NB * 512];
__device__ float z_g[NB * 256];
__device__ float up_g[(size_t)NB * 6400];
__device__ float protoT_g[256 * 512];                // [d][p]
__device__ float pp_g[512];                          // sum_d proto^2
__device__ float w3t_g[256 * 144];                   // [(c*9+tap)][oc]
__device__ float wd1t_g[256 * 144];                  // [c][tap*16+o]

// ---------------- packed fp32x2 helpers (sm_100+) ----------------
static __device__ __forceinline__ unsigned long long ffma2(
    unsigned long long a, unsigned long long b, unsigned long long c) {
    unsigned long long d;
    asm("fma.rn.f32x2 %0, %1, %2, %3;" : "=l"(d) : "l"(a), "l"(b), "l"(c));
    return d;
}
static __device__ __forceinline__ unsigned long long pack2(float x, float y) {
    unsigned long long r;
    asm("mov.b64 %0, {%1, %2};" : "=l"(r) : "f"(x), "f"(y));
    return r;
}
static __device__ __forceinline__ float2 unpack2(unsigned long long v) {
    float2 r;
    asm("mov.b64 {%0, %1}, %2;" : "=f"(r.x), "=f"(r.y) : "l"(v));
    return r;
}

// ---------------- tf32 helpers ----------------
static __device__ __forceinline__ void cvt_hilo(float x, uint32_t& hi, uint32_t& lo) {
    uint32_t h;
    asm("cvt.rna.tf32.f32 %0, %1;" : "=r"(h) : "f"(x));
    float hf = __uint_as_float(h);
    float l = x - hf;
    asm("cvt.rna.tf32.f32 %0, %1;" : "=r"(lo) : "f"(l));
    hi = h;
}
static __device__ __forceinline__ void mma_tf32(float* c, const uint32_t* a, const uint32_t* b) {
    asm volatile(
        "mma.sync.aligned.m16n8k8.row.col.f32.tf32.tf32.f32 "
        "{%0,%1,%2,%3}, {%4,%5,%6,%7}, {%8,%9}, {%0,%1,%2,%3};"
        : "+f"(c[0]), "+f"(c[1]), "+f"(c[2]), "+f"(c[3])
        : "r"(a[0]), "r"(a[1]), "r"(a[2]), "r"(a[3]), "r"(b[0]), "r"(b[1]));
}

// ---------------------------------------------------------------------------
// prep: weight transposes + proto norms
// ---------------------------------------------------------------------------
__global__ void prep_kernel(const float* __restrict__ proto,
                            const float* __restrict__ w3,
                            const float* __restrict__ wd1)
{
    int stride = gridDim.x * blockDim.x;
    int tid = blockIdx.x * blockDim.x + threadIdx.x;
    for (int i = tid; i < 512 * 256; i += stride) {
        int d = i >> 9, p = i & 511;
        protoT_g[i] = proto[p * 256 + d];
    }
    for (int p = tid; p < 512; p += stride) {
        float s = 0.f;
        for (int d = 0; d < 256; d++) {
            float v = proto[p * 256 + d];
            s += v * v;
        }
        pp_g[p] = s;
    }
    for (int i = tid; i < 256 * 144; i += stride) {
        int o = i & 255, ct = i >> 8;
        int c = ct / 9, tap = ct - c * 9;
        w3t_g[i] = w3[o * 144 + c * 9 + tap];
    }
    for (int i = tid; i < 256 * 144; i += stride) {
        int o = i & 15, ct = i >> 4;
        int c = ct / 9, tap = ct - c * 9;
        wd1t_g[c * 144 + tap * 16 + o] = wd1[c * 144 + o * 9 + tap];
    }
}

// ---------------------------------------------------------------------------
// enc12: conv1 + conv2, one block per image
// ---------------------------------------------------------------------------
__global__ __launch_bounds__(128) void enc12_kernel(
    const float* __restrict__ x,
    const float* __restrict__ w1, const float* __restrict__ b1,
    const float* __restrict__ w2, const float* __restrict__ b2,
    const float* __restrict__ g2, const float* __restrict__ bt2)
{
    __shared__ float xs[784];
    __shared__ float h1s[8 * 196];
    const int b = blockIdx.x;
    const int t = threadIdx.x;

    const float* xb = x + b * 784;
    for (int i = t; i < 784; i += 128) xs[i] = xb[i];
    __syncthreads();

    for (int idx = t; idx < 1568; idx += 128) {
        int o = idx / 196, r = idx % 196, i = r / 14, j = r % 14;
        float acc = b1[o];
        #pragma unroll
        for (int ky = 0; ky < 3; ky++) {
            int y = 2 * i - 1 + ky;
            if ((unsigned)y >= 28u) continue;
            #pragma unroll
            for (int kx = 0; kx < 3; kx++) {
                int xx = 2 * j - 1 + kx;
                if ((unsigned)xx >= 28u) continue;
                acc += xs[y * 28 + xx] * w1[o * 9 + ky * 3 + kx];
            }
        }
        h1s[idx] = fmaxf(acc, 0.f);
    }
    __syncthreads();

    const float rs = rsqrtf(1.f + BEPS);
    for (int idx = t; idx < 784; idx += 128) {
        int o = idx / 49, r = idx % 49, i = r / 7, j = r % 7;
        float acc = 0.f;
        for (int c = 0; c < 8; c++) {
            #pragma unroll
            for (int ky = 0; ky < 3; ky++) {
                int y = 2 * i - 1 + ky;
                if ((unsigned)y >= 14u) continue;
                #pragma unroll
                for (int kx = 0; kx < 3; kx++) {
                    int xx = 2 * j - 1 + kx;
                    if ((unsigned)xx >= 14u) continue;
                    acc += h1s[c * 196 + y * 14 + xx] * w2[((o * 8 + c) * 3 + ky) * 3 + kx];
                }
            }
        }
        float s = g2[o] * rs;
        h2_g[b * 784 + idx] = fmaxf((acc + b2[o]) * s + bt2[o], 0.f);
    }
}

// ---------------------------------------------------------------------------
// conv3: 16->256 k3 s1 p0, 7->5; writes h3 transposed [(b*25+pos)][d]
// ---------------------------------------------------------------------------
__global__ __launch_bounds__(256, 2) void conv3_kernel(const float* __restrict__ b3)
{
    __shared__ float h2s[784];
    const int b = blockIdx.x;
    const int t = threadIdx.x;

    for (int i = t; i < 784; i += 256) h2s[i] = h2_g[b * 784 + i];
    __syncthreads();

    float acc[25];
    #pragma unroll
    for (int p = 0; p < 25; p++) acc[p] = 0.f;

    for (int c = 0; c < 16; c++) {
        float w[9];
        #pragma unroll
        for (int tap = 0; tap < 9; tap++) w[tap] = w3t_g[(c * 9 + tap) * 256 + t];
        float h[49];
        #pragma unroll
        for (int i = 0; i < 49; i++) h[i] = h2s[c * 49 + i];
        #pragma unroll
        for (int ky = 0; ky < 3; ky++)
            #pragma unroll
            for (int kx = 0; kx < 3; kx++) {
                float wv = w[ky * 3 + kx];
                #pragma unroll
                for (int i = 0; i < 5; i++)
                    #pragma unroll
                    for (int j = 0; j < 5; j++)
                        acc[i * 5 + j] += wv * h[(i + ky) * 7 + (j + kx)];
            }
    }
    float bb = b3[t];
    #pragma unroll
    for (int p = 0; p < 25; p++)
        h3T_g[((size_t)b * 25 + p) * 256 + t] = fmaxf(acc[p] + bb, 0.f);
}

// ===========================================================================
// 3xTF32 GEMM core: block 128x128, 8 warps (4 m-warps x 2 n-warps),
// warp tile 32x64, k-chunk 32. Raw fp32 in smem; tf32 hi/lo split in regs.
// ===========================================================================
#define AS_STRIDE 36
#define BS_STRIDE 132

// xp GEMM: C[102400x512] = h3T[102400x256] * protoT[256x512]
__global__ __launch_bounds__(256, 2) void xp_gemm_kernel()
{
    __shared__ float As[128 * AS_STRIDE];
    __shared__ float Bs[32 * BS_STRIDE];

    const int t = threadIdx.x;
    const int lane = t & 31, wid = t >> 5;
    const int wm = wid & 3, wn = wid >> 2;
    const int bm = blockIdx.y * 128;
    const int bn = blockIdx.x * 128;

    float acc[2][8][4];
    #pragma unroll
    for (int i = 0; i < 2; i++)
        #pragma unroll
        for (int j = 0; j < 8; j++)
            #pragma unroll
            for (int k = 0; k < 4; k++) acc[i][j][k] = 0.f;

    const int ar = t >> 1, ak = (t & 1) * 16;       // A loader: row 0..127, k half
    const int br = t >> 3, bn16 = (t & 7) * 16;     // B loader: k row 0..31, n chunk

    for (int k0 = 0; k0 < 256; k0 += 32) {
        const float* asrc = &h3T_g[(size_t)(bm + ar) * 256 + k0 + ak];
        const float* bsrc = &protoT_g[(size_t)(k0 + br) * 512 + bn + bn16];
        float4 av0 = *(const float4*)asrc;
        float4 av1 = *(const float4*)(asrc + 4);
        float4 av2 = *(const float4*)(asrc + 8);
        float4 av3 = *(const float4*)(asrc + 12);
        float4 bv0 = *(const float4*)bsrc;
        float4 bv1 = *(const float4*)(bsrc + 4);
        float4 bv2 = *(const float4*)(bsrc + 8);
        float4 bv3 = *(const float4*)(bsrc + 12);
        __syncthreads();
        *(float4*)&As[ar * AS_STRIDE + ak]      = av0;
        *(float4*)&As[ar * AS_STRIDE + ak + 4]  = av1;
        *(float4*)&As[ar * AS_STRIDE + ak + 8]  = av2;
        *(float4*)&As[ar * AS_STRIDE + ak + 12] = av3;
        *(float4*)&Bs[br * BS_STRIDE + bn16]      = bv0;
        *(float4*)&Bs[br * BS_STRIDE + bn16 + 4]  = bv1;
        *(float4*)&Bs[br * BS_STRIDE + bn16 + 8]  = bv2;
        *(float4*)&Bs[br * BS_STRIDE + bn16 + 12] = bv3;
        __syncthreads();

        #pragma unroll
        for (int ks = 0; ks < 4; ks++) {
            const int col = ks * 8 + (lane & 3);
            uint32_t ah[2][4], al[2][4];
            #pragma unroll
            for (int ms = 0; ms < 2; ms++) {
                int mb = wm * 32 + ms * 16 + (lane >> 2);
                float x0 = As[mb * AS_STRIDE + col];
                float x1 = As[(mb + 8) * AS_STRIDE + col];
                float x2 = As[mb * AS_STRIDE + col + 4];
                float x3 = As[(mb + 8) * AS_STRIDE + col + 4];
                cvt_hilo(x0, ah[ms][0], al[ms][0]);
                cvt_hilo(x1, ah[ms][1], al[ms][1]);
                cvt_hilo(x2, ah[ms][2], al[ms][2]);
                cvt_hilo(x3, ah[ms][3], al[ms][3]);
            }
            const int row = ks * 8 + (lane & 3);
            #pragma unroll
            for (int nt = 0; nt < 8; nt++) {
                int nb = wn * 64 + nt * 8 + (lane >> 2);
                float y0 = Bs[row * BS_STRIDE + nb];
                float y1 = Bs[(row + 4) * BS_STRIDE + nb];
                uint32_t bh[2], bl[2];
                cvt_hilo(y0, bh[0], bl[0]);
                cvt_hilo(y1, bh[1], bl[1]);
                #pragma unroll
                for (int ms = 0; ms < 2; ms++) {
                    mma_tf32(acc[ms][nt], ah[ms], bh);
                    mma_tf32(acc[ms][nt], ah[ms], bl);
                    mma_tf32(acc[ms][nt], al[ms], bh);
                }
            }
        }
    }

    #pragma unroll
    for (int ms = 0; ms < 2; ms++)
        #pragma unroll
        for (int nt = 0; nt < 8; nt++) {
            int row0 = bm + wm * 32 + ms * 16 + (lane >> 2);
            int col0 = bn + wn * 64 + nt * 8 + 2 * (lane & 3);
            *(float2*)&xp_g[(size_t)row0 * 512 + col0] =
                make_float2(acc[ms][nt][0], acc[ms][nt][1]);
            *(float2*)&xp_g[(size_t)(row0 + 8) * 512 + col0] =
                make_float2(acc[ms][nt][2], acc[ms][nt][3]);
        }
}

// up GEMM: up[4096x6400] = relu(BN(z[4096x256] * wup[256x6400]))
__global__ __launch_bounds__(256, 2) void up_gemm_kernel(
    const float* __restrict__ wup, const float* __restrict__ bup,
    const float* __restrict__ gup, const float* __restrict__ btup)
{
    __shared__ float As[128 * AS_STRIDE];
    __shared__ float Bs[32 * BS_STRIDE];

    const int t = threadIdx.x;
    const int lane = t & 31, wid = t >> 5;
    const int wm = wid & 3, wn = wid >> 2;
    const int bm = blockIdx.y * 128;
    const int bn = blockIdx.x * 128;

    float acc[2][8][4];
    #pragma unroll
    for (int i = 0; i < 2; i++)
        #pragma unroll
        for (int j = 0; j < 8; j++)
            #pragma unroll
            for (int k = 0; k < 4; k++) acc[i][j][k] = 0.f;

    const int ar = t >> 1, ak = (t & 1) * 16;
    const int br = t >> 3, bn16 = (t & 7) * 16;

    for (int k0 = 0; k0 < 256; k0 += 32) {
        const float* asrc = &z_g[(size_t)(bm + ar) * 256 + k0 + ak];
        const float* bsrc = &wup[(size_t)(k0 + br) * 6400 + bn + bn16];
        float4 av0 = *(const float4*)asrc;
        float4 av1 = *(const float4*)(asrc + 4);
        float4 av2 = *(const float4*)(asrc + 8);
        float4 av3 = *(const float4*)(asrc + 12);
        float4 bv0 = *(const float4*)bsrc;
        float4 bv1 = *(const float4*)(bsrc + 4);
        float4 bv2 = *(const float4*)(bsrc + 8);
        float4 bv3 = *(const float4*)(bsrc + 12);
        __syncthreads();
        *(float4*)&As[ar * AS_STRIDE + ak]      = av0;
        *(float4*)&As[ar * AS_STRIDE + ak + 4]  = av1;
        *(float4*)&As[ar * AS_STRIDE + ak + 8]  = av2;
        *(float4*)&As[ar * AS_STRIDE + ak + 12] = av3;
        *(float4*)&Bs[br * BS_STRIDE + bn16]      = bv0;
        *(float4*)&Bs[br * BS_STRIDE + bn16 + 4]  = bv1;
        *(float4*)&Bs[br * BS_STRIDE + bn16 + 8]  = bv2;
        *(float4*)&Bs[br * BS_STRIDE + bn16 + 12] = bv3;
        __syncthreads();

        #pragma unroll
        for (int ks = 0; ks < 4; ks++) {
            const int col = ks * 8 + (lane & 3);
            uint32_t ah[2][4], al[2][4];
            #pragma unroll
            for (int ms = 0; ms < 2; ms++) {
                int mb = wm * 32 + ms * 16 + (lane >> 2);
                float x0 = As[mb * AS_STRIDE + col];
                float x1 = As[(mb + 8) * AS_STRIDE + col];
                float x2 = As[mb * AS_STRIDE + col + 4];
                float x3 = As[(mb + 8) * AS_STRIDE + col + 4];
                cvt_hilo(x0, ah[ms][0], al[ms][0]);
                cvt_hilo(x1, ah[ms][1], al[ms][1]);
                cvt_hilo(x2, ah[ms][2], al[ms][2]);
                cvt_hilo(x3, ah[ms][3], al[ms][3]);
            }
            const int row = ks * 8 + (lane & 3);
            #pragma unroll
            for (int nt = 0; nt < 8; nt++) {
                int nb = wn * 64 + nt * 8 + (lane >> 2);
                float y0 = Bs[row * BS_STRIDE + nb];
                float y1 = Bs[(row + 4) * BS_STRIDE + nb];
                uint32_t bh[2], bl[2];
                cvt_hilo(y0, bh[0], bl[0]);
                cvt_hilo(y1, bh[1], bl[1]);
                #pragma unroll
                for (int ms = 0; ms < 2; ms++) {
                    mma_tf32(acc[ms][nt], ah[ms], bh);
                    mma_tf32(acc[ms][nt], ah[ms], bl);
                    mma_tf32(acc[ms][nt], al[ms], bh);
                }
            }
        }
    }

    const float rsc = rsqrtf(1.f + BEPS);
    #pragma unroll
    for (int ms = 0; ms < 2; ms++)
        #pragma unroll
        for (int nt = 0; nt < 8; nt++) {
            int row0 = bm + wm * 32 + ms * 16 + (lane >> 2);
            int col0 = bn + wn * 64 + nt * 8 + 2 * (lane & 3);
            int o0 = col0 / 25, o1 = (col0 + 1) / 25;
            float s0 = gup[o0] * rsc, s1 = gup[o1] * rsc;
            float bi0 = bup[o0] * s0 + btup[o0];
            float bi1 = bup[o1] * s1 + btup[o1];
            *(float2*)&up_g[(size_t)row0 * 6400 + col0] =
                make_float2(fmaxf(acc[ms][nt][0] * s0 + bi0, 0.f),
                            fmaxf(acc[ms][nt][1] * s1 + bi1, 0.f));
            *(float2*)&up_g[(size_t)(row0 + 8) * 6400 + col0] =
                make_float2(fmaxf(acc[ms][nt][2] * s0 + bi0, 0.f),
                            fmaxf(acc[ms][nt][3] * s1 + bi1, 0.f));
        }
}

// ---------------------------------------------------------------------------
// minsoftmax: distances from xp, min over pos, softmax -> w_g, minD out.
// ---------------------------------------------------------------------------
__global__ __launch_bounds__(512) void minsoftmax_kernel(float* __restrict__ out_minD)
{
    __shared__ float x2s[25];
    __shared__ float red[32];

    const int b = blockIdx.x;
    const int t = threadIdx.x;
    const int lane = t & 31, wid = t >> 5;

    for (int pos = wid; pos < 25; pos += 16) {
        const float* row = &h3T_g[((size_t)b * 25 + pos) * 256];
        float s = 0.f;
        #pragma unroll
        for (int j = 0; j < 8; j++) {
            float v = row[lane + 32 * j];
            s += v * v;
        }
        #pragma unroll
        for (int off = 16; off; off >>= 1) s += __shfl_xor_sync(0xffffffffu, s, off);
        if (!lane) x2s[pos] = s;
    }
    __syncthreads();

    const float pp = pp_g[t];
    float m = 3.0e38f;
    #pragma unroll 5
    for (int pos = 0; pos < 25; pos++) {
        float xv = xp_g[((size_t)b * 25 + pos) * 512 + t];
        float d = fmaxf(x2s[pos] - 2.f * xv + pp, 0.f);
        m = fminf(m, d);
    }
    out_minD[(size_t)b * 512 + t] = m;

    float a = -m;
    float v = a;
    #pragma unroll
    for (int off = 16; off; off >>= 1) v = fmaxf(v, __shfl_xor_sync(0xffffffffu, v, off));
    if (!lane) red[wid] = v;
    __syncthreads();
    if (t == 0) {
        float r = red[0];
        for (int i = 1; i < 16; i++) r = fmaxf(r, red[i]);
        red[16] = r;
    }
    __syncthreads();
    float amax = red[16];
    float e = expf(a - amax);
    float sv = e;
    #pragma unroll
    for (int off = 16; off; off >>= 1) sv += __shfl_xor_sync(0xffffffffu, sv, off);
    __syncthreads();
    if (!lane) red[wid] = sv;
    __syncthreads();
    if (t == 0) {
        float r = 0.f;
        for (int i = 0; i < 16; i++) r += red[i];
        red[16] = r;
    }
    __syncthreads();
    w_g[(size_t)b * 512 + t] = e * (1.f / red[16]);
}

// ---------------------------------------------------------------------------
// z GEMM (FFMA f32x2): z[4096x256] = w[4096x512] * proto[512x256]
// ---------------------------------------------------------------------------
__global__ __launch_bounds__(256) void z_gemm_kernel(const float* __restrict__ proto)
{
    __shared__ __align__(16) float As2[16][128];
    __shared__ __align__(16) float Bs2[16][64];
    const int bn = blockIdx.x * 64;
    const int bm = blockIdx.y * 128;
    const int t = threadIdx.x;
    const int tx = t & 15, ty = t >> 4;

    unsigned long long acc[4][4];
    #pragma unroll
    for (int i = 0; i < 4; i++)
        #pragma unroll
        for (int j = 0; j < 4; j++) acc[i][j] = 0ull;

    for (int k0 = 0; k0 < 512; k0 += 16) {
        #pragma unroll
        for (int s = t; s < 512; s += 256) {
            int r = s >> 2, kq = (s & 3) << 2;
            float4 v = *(const float4*)&w_g[(size_t)(bm + r) * 512 + k0 + kq];
            As2[kq + 0][r] = v.x; As2[kq + 1][r] = v.y;
            As2[kq + 2][r] = v.z; As2[kq + 3][r] = v.w;
        }
        {
            int kk = t >> 4, n4 = (t & 15) << 2;
            *(float4*)&Bs2[kk][n4] = *(const float4*)&proto[(size_t)(k0 + kk) * 256 + bn + n4];
        }
        __syncthreads();
        #pragma unroll
        for (int kk = 0; kk < 16; kk++) {
            ulonglong2 a01 = *(const ulonglong2*)&As2[kk][ty * 8];
            ulonglong2 a23 = *(const ulonglong2*)&As2[kk][ty * 8 + 4];
            float4 bv = *(const float4*)&Bs2[kk][tx * 4];
            unsigned long long bd0 = pack2(bv.x, bv.x), bd1 = pack2(bv.y, bv.y);
            unsigned long long bd2 = pack2(bv.z, bv.z), bd3 = pack2(bv.w, bv.w);
            acc[0][0] = ffma2(a01.x, bd0, acc[0][0]); acc[0][1] = ffma2(a01.x, bd1, acc[0][1]);
            acc[0][2] = ffma2(a01.x, bd2, acc[0][2]); acc[0][3] = ffma2(a01.x, bd3, acc[0][3]);
            acc[1][0] = ffma2(a01.y, bd0, acc[1][0]); acc[1][1] = ffma2(a01.y, bd1, acc[1][1]);
            acc[1][2] = ffma2(a01.y, bd2, acc[1][2]); acc[1][3] = ffma2(a01.y, bd3, acc[1][3]);
            acc[2][0] = ffma2(a23.x, bd0, acc[2][0]); acc[2][1] = ffma2(a23.x, bd1, acc[2][1]);
            acc[2][2] = ffma2(a23.x, bd2, acc[2][2]); acc[2][3] = ffma2(a23.x, bd3, acc[2][3]);
            acc[3][0] = ffma2(a23.y, bd0, acc[3][0]); acc[3][1] = ffma2(a23.y, bd1, acc[3][1]);
            acc[3][2] = ffma2(a23.y, bd2, acc[3][2]); acc[3][3] = ffma2(a23.y, bd3, acc[3][3]);
        }
        __syncthreads();
    }

    #pragma unroll
    for (int mp = 0; mp < 4; mp++) {
        int m0 = bm + ty * 8 + mp * 2;
        float2 f0 = unpack2(acc[mp][0]), f1 = unpack2(acc[mp][1]);
        float2 f2 = unpack2(acc[mp][2]), f3 = unpack2(acc[mp][3]);
        float4 r0 = make_float4(f0.x, f1.x, f2.x, f3.x);
        float4 r1 = make_float4(f0.y, f1.y, f2.y, f3.y);
        *(float4*)&z_g[(size_t)m0 * 256 + bn + tx * 4] = r0;
        *(float4*)&z_g[(size_t)(m0 + 1) * 256 + bn + tx * 4] = r1;
    }
}

// ---------------------------------------------------------------------------
// dec: transposed convs. 4 images per block, 256 threads.
// ---------------------------------------------------------------------------
__global__ __launch_bounds__(256) void dec_kernel(
    const float* __restrict__ bd1,
    const float* __restrict__ gd1, const float* __restrict__ btd1,
    const float* __restrict__ wd2, const float* __restrict__ bd2,
    const float* __restrict__ gd2, const float* __restrict__ btd2,
    const float* __restrict__ wd3, const float* __restrict__ bd3,
    float* __restrict__ out)
{
    extern __shared__ float sm[];
    float* ups  = sm;                 // 25600
    float* wts  = ups + 25600;        // 4608
    float* d1s  = wts + 4608;         // 3136
    float* d2s  = d1s + 3136;         // 6272
    float* wd2s = d2s + 6272;         // 1152
    float* wd3s = wd2s + 1152;        // 72

    const int t = threadIdx.x;
    const int b0 = blockIdx.x * 4;
    const float rs = rsqrtf(1.f + BEPS);

    for (int i = t; i < 25600; i += 256) ups[i] = up_g[(size_t)b0 * 6400 + i];
    for (int i = t; i < 1152; i += 256) wd2s[i] = wd2[i];
    if (t < 72) wd3s[t] = wd3[t];

    const int pos = t % 49;
    const int og = t / 49;
    const int oi = pos / 7, oj = pos % 7;
    const int y0 = max(oi - 2, 0), y1 = min(oi, 4);
    const int x0 = max(oj - 2, 0), x1 = min(oj, 4);

    float acc[4][4];
    #pragma unroll
    for (int a = 0; a < 4; a++)
        #pragma unroll
        for (int o = 0; o < 4; o++) acc[a][o] = 0.f;

    for (int c0 = 0; c0 < 256; c0 += 32) {
        __syncthreads();
        for (int i = t; i < 4608; i += 256) wts[i] = wd1t_g[c0 * 144 + i];
        __syncthreads();
        if (t < 196) {
            for (int c = 0; c < 32; c++) {
                int cb = (c0 + c) * 25;
                const float* wb = &wts[c * 144];
                for (int y = y0; y <= y1; y++) {
                    int ki = oi - y;
                    for (int xx = x0; xx <= x1; xx++) {
                        int kj = oj - xx;
                        float4 w4 = *(const float4*)&wb[(ki * 3 + kj) * 16 + og * 4];
                        float u0 = ups[0 * 6400 + cb + y * 5 + xx];
                        float u1 = ups[1 * 6400 + cb + y * 5 + xx];
                        float u2 = ups[2 * 6400 + cb + y * 5 + xx];
                        float u3 = ups[3 * 6400 + cb + y * 5 + xx];
                        acc[0][0] += u0 * w4.x; acc[0][1] += u0 * w4.y;
                        acc[0][2] += u0 * w4.z; acc[0][3] += u0 * w4.w;
                        acc[1][0] += u1 * w4.x; acc[1][1] += u1 * w4.y;
                        acc[1][2] += u1 * w4.z; acc[1][3] += u1 * w4.w;
                        acc[2][0] += u2 * w4.x; acc[2][1] += u2 * w4.y;
                        acc[2][2] += u2 * w4.z; acc[2][3] += u2 * w4.w;
                        acc[3][0] += u3 * w4.x; acc[3][1] += u3 * w4.y;
                        acc[3][2] += u3 * w4.z; acc[3][3] += u3 * w4.w;
                    }
                }
            }
        }
    }
    if (t < 196) {
        #pragma unroll
        for (int oo = 0; oo < 4; oo++) {
            int o = og * 4 + oo;
            float s = gd1[o] * rs;
            float bias = bd1[o] * s + btd1[o];
            #pragma unroll
            for (int a = 0; a < 4; a++)
                d1s[a * 784 + o * 49 + pos] = fmaxf(acc[a][oo] * s + bias, 0.f);
        }
    }
    __syncthreads();

    if (t < 196) {
        float acc2[4][8];
        #pragma unroll
        for (int a = 0; a < 4; a++)
            #pragma unroll
            for (int o = 0; o < 8; o++) acc2[a][o] = 0.f;
        int i = t / 14, j = t % 14;
        int ylo = i / 2, yhi = min((i + 1) / 2, 6);
        int xlo = j / 2, xhi = min((j + 1) / 2, 6);
        for (int c = 0; c < 16; c++) {
            for (int y = ylo; y <= yhi; y++) {
                int ki = i - 2 * y + 1;
                for (int xx = xlo; xx <= xhi; xx++) {
                    int kj = j - 2 * xx + 1;
                    float u0 = d1s[0 * 784 + c * 49 + y * 7 + xx];
                    float u1 = d1s[1 * 784 + c * 49 + y * 7 + xx];
                    float u2 = d1s[2 * 784 + c * 49 + y * 7 + xx];
                    float u3 = d1s[3 * 784 + c * 49 + y * 7 + xx];
                    #pragma unroll
                    for (int o = 0; o < 8; o++) {
                        float wv = wd2s[((c * 8 + o) * 3 + ki) * 3 + kj];
                        acc2[0][o] += u0 * wv;
                        acc2[1][o] += u1 * wv;
                        acc2[2][o] += u2 * wv;
                        acc2[3][o] += u3 * wv;
                    }
                }
            }
        }
        #pragma unroll
        for (int o = 0; o < 8; o++) {
            float s = gd2[o] * rs;
            float bias = bd2[o] * s + btd2[o];
            #pragma unroll
            for (int a = 0; a < 4; a++)
                d2s[a * 1568 + o * 196 + t] = fmaxf(acc2[a][o] * s + bias, 0.f);
        }
    }
    __syncthreads();

    const float bb3 = bd3[0];
    for (int idx = t; idx < 3136; idx += 256) {
        int a = idx / 784, p = idx % 784, i = p / 28, j = p % 28;
        int ylo = i / 2, yhi = min((i + 1) / 2, 13);
        int xlo = j / 2, xhi = min((j + 1) / 2, 13);
        float acc3 = bb3;
        for (int c = 0; c < 8; c++) {
            for (int y = ylo; y <= yhi; y++) {
                int ki = i - 2 * y + 1;
                for (int xx = xlo; xx <= xhi; xx++) {
                    int kj = j - 2 * xx + 1;
                    acc3 += d2s[a * 1568 + c * 196 + y * 14 + xx] * wd3s[c * 9 + ki * 3 + kj];
                }
            }
        }
        out[(size_t)(b0 + a) * 784 + p] = 1.f / (1.f + expf(-acc3));
    }
}

// ---------------------------------------------------------------------------
extern "C" void kernel_launch(void* const* d_in, const int* in_sizes, int n_in,
                              void* d_out, int out_size)
{
    const float* x     = (const float*)d_in[0];
    const float* w1    = (const float*)d_in[1];
    const float* b1    = (const float*)d_in[2];
    const float* w2    = (const float*)d_in[3];
    const float* b2    = (const float*)d_in[4];
    const float* g2    = (const float*)d_in[5];
    const float* bt2   = (const float*)d_in[6];
    const float* w3    = (const float*)d_in[7];
    const float* b3    = (const float*)d_in[8];
    const float* proto = (const float*)d_in[9];
    const float* wup   = (const float*)d_in[10];
    const float* bup   = (const float*)d_in[11];
    const float* gup   = (const float*)d_in[12];
    const float* btup  = (const float*)d_in[13];
    const float* wd1   = (const float*)d_in[14];
    const float* bd1   = (const float*)d_in[15];
    const float* gd1   = (const float*)d_in[16];
    const float* btd1  = (const float*)d_in[17];
    const float* wd2   = (const float*)d_in[18];
    const float* bd2   = (const float*)d_in[19];
    const float* gd2   = (const float*)d_in[20];
    const float* btd2  = (const float*)d_in[21];
    const float* wd3   = (const float*)d_in[22];
    const float* bd3   = (const float*)d_in[23];

    float* out  = (float*)d_out;                 // (4096,1,28,28)
    float* minD = out + (size_t)NB * 784;        // (4096,512)

    prep_kernel<<<128, 256>>>(proto, w3, wd1);
    enc12_kernel<<<NB, 128>>>(x, w1, b1, w2, b2, g2, bt2);
    conv3_kernel<<<NB, 256>>>(b3);

    dim3 gx(512 / 128, (NB * 25) / 128);         // (4, 800)
    xp_gemm_kernel<<<gx, 256>>>();

    minsoftmax_kernel<<<NB, 512>>>(minD);

    dim3 gz(256 / 64, NB / 128);
    z_gemm_kernel<<<gz, 256>>>(proto);

    dim3 gu(6400 / 128, NB / 128);               // (50, 32)
    up_gemm_kernel<<<gu, 256>>>(wup, bup, gup, btup);

    size_t smem = (size_t)(25600 + 4608 + 3136 + 6272 + 1152 + 72) * sizeof(float);
    cudaFuncSetAttribute(dec_kernel, cudaFuncAttributeMaxDynamicSharedMemorySize, (int)smem);
    dec_kernel<<<NB / 4, 256, smem>>>(bd1, gd1, btd1,
                                      wd2, bd2, gd2, btd2,
                                      wd3, bd3, out);
}

// round 6
// speedup vs baseline: 2.2330x; 1.8700x over previous
#include <cuda_runtime.h>
#include <math.h>
#include <stdint.h>

#define BEPS 1e-5f
#define NB 4096

// ---------------- scratch (allocation-free) ----------------
__device__ float h2_g[NB * 784];
__device__ float h3T_g[(size_t)NB * 25 * 256];       // [(b*25+pos)][d]
__device__ float xp_g[(size_t)NB * 25 * 512];        // [(b*25+pos)][p]
__device__ float w_g[NB * 512];
__device__ float z_g[NB * 256];
__device__ float up2_g[(size_t)NB * 6400];           // [(b*25+pos)][c]  (permuted layout)
__device__ float G_g[(size_t)NB * 25 * 144];         // [(b*25+pos)][o*9+tap]
__device__ float protoT_g[256 * 512];                // [d][p]
__device__ float pp_g[512];                          // sum_d proto^2
__device__ float w3t_g[256 * 144];                   // [(c*9+tap)][oc]
__device__ float wupPT_g[256 * 6400];                // [k][pos*256+c] = wup[k][c*25+pos]

// ---------------- packed fp32x2 helpers (sm_100+) ----------------
static __device__ __forceinline__ unsigned long long ffma2(
    unsigned long long a, unsigned long long b, unsigned long long c) {
    unsigned long long d;
    asm("fma.rn.f32x2 %0, %1, %2, %3;" : "=l"(d) : "l"(a), "l"(b), "l"(c));
    return d;
}
static __device__ __forceinline__ unsigned long long pack2(float x, float y) {
    unsigned long long r;
    asm("mov.b64 %0, {%1, %2};" : "=l"(r) : "f"(x), "f"(y));
    return r;
}
static __device__ __forceinline__ float2 unpack2(unsigned long long v) {
    float2 r;
    asm("mov.b64 {%0, %1}, %2;" : "=f"(r.x), "=f"(r.y) : "l"(v));
    return r;
}

// ---------------- tf32 helpers ----------------
static __device__ __forceinline__ void cvt_hilo(float x, uint32_t& hi, uint32_t& lo) {
    uint32_t h;
    asm("cvt.rna.tf32.f32 %0, %1;" : "=r"(h) : "f"(x));
    float hf = __uint_as_float(h);
    float l = x - hf;
    asm("cvt.rna.tf32.f32 %0, %1;" : "=r"(lo) : "f"(l));
    hi = h;
}
static __device__ __forceinline__ void mma_tf32(float* c, const uint32_t* a, const uint32_t* b) {
    asm volatile(
        "mma.sync.aligned.m16n8k8.row.col.f32.tf32.tf32.f32 "
        "{%0,%1,%2,%3}, {%4,%5,%6,%7}, {%8,%9}, {%0,%1,%2,%3};"
        : "+f"(c[0]), "+f"(c[1]), "+f"(c[2]), "+f"(c[3])
        : "r"(a[0]), "r"(a[1]), "r"(a[2]), "r"(a[3]), "r"(b[0]), "r"(b[1]));
}

// ---------------------------------------------------------------------------
// prep: transposes + proto norms + wup column permutation
// ---------------------------------------------------------------------------
__global__ void prep_kernel(const float* __restrict__ proto,
                            const float* __restrict__ w3,
                            const float* __restrict__ wup)
{
    int stride = gridDim.x * blockDim.x;
    int tid = blockIdx.x * blockDim.x + threadIdx.x;
    for (int i = tid; i < 512 * 256; i += stride) {
        int d = i >> 9, p = i & 511;
        protoT_g[i] = proto[p * 256 + d];
    }
    for (int p = tid; p < 512; p += stride) {
        float s = 0.f;
        for (int d = 0; d < 256; d++) {
            float v = proto[p * 256 + d];
            s += v * v;
        }
        pp_g[p] = s;
    }
    for (int i = tid; i < 256 * 144; i += stride) {
        int o = i & 255, ct = i >> 8;
        int c = ct / 9, tap = ct - c * 9;
        w3t_g[i] = w3[o * 144 + c * 9 + tap];
    }
    // wupPT[k*6400 + pos*256 + c] = wup[k*6400 + c*25 + pos]
    for (int i = tid; i < 256 * 6400; i += stride) {
        int k = i / 6400, rr = i % 6400;
        int pos = rr >> 8, c = rr & 255;
        wupPT_g[i] = wup[k * 6400 + c * 25 + pos];
    }
}

// ---------------------------------------------------------------------------
// enc12: conv1 + conv2, one block per image
// ---------------------------------------------------------------------------
__global__ __launch_bounds__(128) void enc12_kernel(
    const float* __restrict__ x,
    const float* __restrict__ w1, const float* __restrict__ b1,
    const float* __restrict__ w2, const float* __restrict__ b2,
    const float* __restrict__ g2, const float* __restrict__ bt2)
{
    __shared__ float xs[784];
    __shared__ float h1s[8 * 196];
    const int b = blockIdx.x;
    const int t = threadIdx.x;

    const float* xb = x + b * 784;
    for (int i = t; i < 784; i += 128) xs[i] = xb[i];
    __syncthreads();

    for (int idx = t; idx < 1568; idx += 128) {
        int o = idx / 196, r = idx % 196, i = r / 14, j = r % 14;
        float acc = b1[o];
        #pragma unroll
        for (int ky = 0; ky < 3; ky++) {
            int y = 2 * i - 1 + ky;
            if ((unsigned)y >= 28u) continue;
            #pragma unroll
            for (int kx = 0; kx < 3; kx++) {
                int xx = 2 * j - 1 + kx;
                if ((unsigned)xx >= 28u) continue;
                acc += xs[y * 28 + xx] * w1[o * 9 + ky * 3 + kx];
            }
        }
        h1s[idx] = fmaxf(acc, 0.f);
    }
    __syncthreads();

    const float rs = rsqrtf(1.f + BEPS);
    for (int idx = t; idx < 784; idx += 128) {
        int o = idx / 49, r = idx % 49, i = r / 7, j = r % 7;
        float acc = 0.f;
        for (int c = 0; c < 8; c++) {
            #pragma unroll
            for (int ky = 0; ky < 3; ky++) {
                int y = 2 * i - 1 + ky;
                if ((unsigned)y >= 14u) continue;
                #pragma unroll
                for (int kx = 0; kx < 3; kx++) {
                    int xx = 2 * j - 1 + kx;
                    if ((unsigned)xx >= 14u) continue;
                    acc += h1s[c * 196 + y * 14 + xx] * w2[((o * 8 + c) * 3 + ky) * 3 + kx];
                }
            }
        }
        float s = g2[o] * rs;
        h2_g[b * 784 + idx] = fmaxf((acc + b2[o]) * s + bt2[o], 0.f);
    }
}

// ---------------------------------------------------------------------------
// conv3: 16->256 k3 s1 p0, 7->5; writes h3 transposed [(b*25+pos)][d]
// ---------------------------------------------------------------------------
__global__ __launch_bounds__(256, 2) void conv3_kernel(const float* __restrict__ b3)
{
    __shared__ float h2s[784];
    const int b = blockIdx.x;
    const int t = threadIdx.x;

    for (int i = t; i < 784; i += 256) h2s[i] = h2_g[b * 784 + i];
    __syncthreads();

    float acc[25];
    #pragma unroll
    for (int p = 0; p < 25; p++) acc[p] = 0.f;

    for (int c = 0; c < 16; c++) {
        float w[9];
        #pragma unroll
        for (int tap = 0; tap < 9; tap++) w[tap] = w3t_g[(c * 9 + tap) * 256 + t];
        float h[49];
        #pragma unroll
        for (int i = 0; i < 49; i++) h[i] = h2s[c * 49 + i];
        #pragma unroll
        for (int ky = 0; ky < 3; ky++)
            #pragma unroll
            for (int kx = 0; kx < 3; kx++) {
                float wv = w[ky * 3 + kx];
                #pragma unroll
                for (int i = 0; i < 5; i++)
                    #pragma unroll
                    for (int j = 0; j < 5; j++)
                        acc[i * 5 + j] += wv * h[(i + ky) * 7 + (j + kx)];
            }
    }
    float bb = b3[t];
    #pragma unroll
    for (int p = 0; p < 25; p++)
        h3T_g[((size_t)b * 25 + p) * 256 + t] = fmaxf(acc[p] + bb, 0.f);
}

// ===========================================================================
// 3xTF32 GEMM cores. Raw fp32 in smem; tf32 hi/lo split in registers.
// ===========================================================================
#define AS_STRIDE 36
#define BS_STRIDE 132

// xp GEMM: C[102400x512] = h3T[102400x256] * protoT[256x512]
__global__ __launch_bounds__(256, 2) void xp_gemm_kernel()
{
    __shared__ float As[128 * AS_STRIDE];
    __shared__ float Bs[32 * BS_STRIDE];

    const int t = threadIdx.x;
    const int lane = t & 31, wid = t >> 5;
    const int wm = wid & 3, wn = wid >> 2;
    const int bm = blockIdx.y * 128;
    const int bn = blockIdx.x * 128;

    float acc[2][8][4];
    #pragma unroll
    for (int i = 0; i < 2; i++)
        #pragma unroll
        for (int j = 0; j < 8; j++)
            #pragma unroll
            for (int k = 0; k < 4; k++) acc[i][j][k] = 0.f;

    const int ar = t >> 1, ak = (t & 1) * 16;
    const int br = t >> 3, bn16 = (t & 7) * 16;

    for (int k0 = 0; k0 < 256; k0 += 32) {
        const float* asrc = &h3T_g[(size_t)(bm + ar) * 256 + k0 + ak];
        const float* bsrc = &protoT_g[(size_t)(k0 + br) * 512 + bn + bn16];
        float4 av0 = *(const float4*)asrc;
        float4 av1 = *(const float4*)(asrc + 4);
        float4 av2 = *(const float4*)(asrc + 8);
        float4 av3 = *(const float4*)(asrc + 12);
        float4 bv0 = *(const float4*)bsrc;
        float4 bv1 = *(const float4*)(bsrc + 4);
        float4 bv2 = *(const float4*)(bsrc + 8);
        float4 bv3 = *(const float4*)(bsrc + 12);
        __syncthreads();
        *(float4*)&As[ar * AS_STRIDE + ak]      = av0;
        *(float4*)&As[ar * AS_STRIDE + ak + 4]  = av1;
        *(float4*)&As[ar * AS_STRIDE + ak + 8]  = av2;
        *(float4*)&As[ar * AS_STRIDE + ak + 12] = av3;
        *(float4*)&Bs[br * BS_STRIDE + bn16]      = bv0;
        *(float4*)&Bs[br * BS_STRIDE + bn16 + 4]  = bv1;
        *(float4*)&Bs[br * BS_STRIDE + bn16 + 8]  = bv2;
        *(float4*)&Bs[br * BS_STRIDE + bn16 + 12] = bv3;
        __syncthreads();

        #pragma unroll
        for (int ks = 0; ks < 4; ks++) {
            const int col = ks * 8 + (lane & 3);
            uint32_t ah[2][4], al[2][4];
            #pragma unroll
            for (int ms = 0; ms < 2; ms++) {
                int mb = wm * 32 + ms * 16 + (lane >> 2);
                float x0 = As[mb * AS_STRIDE + col];
                float x1 = As[(mb + 8) * AS_STRIDE + col];
                float x2 = As[mb * AS_STRIDE + col + 4];
                float x3 = As[(mb + 8) * AS_STRIDE + col + 4];
                cvt_hilo(x0, ah[ms][0], al[ms][0]);
                cvt_hilo(x1, ah[ms][1], al[ms][1]);
                cvt_hilo(x2, ah[ms][2], al[ms][2]);
                cvt_hilo(x3, ah[ms][3], al[ms][3]);
            }
            const int row = ks * 8 + (lane & 3);
            #pragma unroll
            for (int nt = 0; nt < 8; nt++) {
                int nb = wn * 64 + nt * 8 + (lane >> 2);
                float y0 = Bs[row * BS_STRIDE + nb];
                float y1 = Bs[(row + 4) * BS_STRIDE + nb];
                uint32_t bh[2], bl[2];
                cvt_hilo(y0, bh[0], bl[0]);
                cvt_hilo(y1, bh[1], bl[1]);
                #pragma unroll
                for (int ms = 0; ms < 2; ms++) {
                    mma_tf32(acc[ms][nt], ah[ms], bh);
                    mma_tf32(acc[ms][nt], ah[ms], bl);
                    mma_tf32(acc[ms][nt], al[ms], bh);
                }
            }
        }
    }

    #pragma unroll
    for (int ms = 0; ms < 2; ms++)
        #pragma unroll
        for (int nt = 0; nt < 8; nt++) {
            int row0 = bm + wm * 32 + ms * 16 + (lane >> 2);
            int col0 = bn + wn * 64 + nt * 8 + 2 * (lane & 3);
            *(float2*)&xp_g[(size_t)row0 * 512 + col0] =
                make_float2(acc[ms][nt][0], acc[ms][nt][1]);
            *(float2*)&xp_g[(size_t)(row0 + 8) * 512 + col0] =
                make_float2(acc[ms][nt][2], acc[ms][nt][3]);
        }
}

// up GEMM: up2[4096*25 rows visited as 4096x... ] -- C row = (b*25+pos) col = c
// up2[102400? no: M=4096 z rows] -> produces up2[(b)*? ] see mapping below.
// Actually: C[4096 x 6400] with rows=b, cols=(pos*256+c); stored to up2 as
// [(b*25+pos)][c] = row-major contiguous since up2_g[((b*25)+pos)*256+c]
//   = up2_g[b*6400 + pos*256 + c].
__global__ __launch_bounds__(256, 2) void up_gemm_kernel(
    const float* __restrict__ bup,
    const float* __restrict__ gup, const float* __restrict__ btup)
{
    __shared__ float As[128 * AS_STRIDE];
    __shared__ float Bs[32 * BS_STRIDE];

    const int t = threadIdx.x;
    const int lane = t & 31, wid = t >> 5;
    const int wm = wid & 3, wn = wid >> 2;
    const int bm = blockIdx.y * 128;
    const int bn = blockIdx.x * 128;

    float acc[2][8][4];
    #pragma unroll
    for (int i = 0; i < 2; i++)
        #pragma unroll
        for (int j = 0; j < 8; j++)
            #pragma unroll
            for (int k = 0; k < 4; k++) acc[i][j][k] = 0.f;

    const int ar = t >> 1, ak = (t & 1) * 16;
    const int br = t >> 3, bn16 = (t & 7) * 16;

    for (int k0 = 0; k0 < 256; k0 += 32) {
        const float* asrc = &z_g[(size_t)(bm + ar) * 256 + k0 + ak];
        const float* bsrc = &wupPT_g[(size_t)(k0 + br) * 6400 + bn + bn16];
        float4 av0 = *(const float4*)asrc;
        float4 av1 = *(const float4*)(asrc + 4);
        float4 av2 = *(const float4*)(asrc + 8);
        float4 av3 = *(const float4*)(asrc + 12);
        float4 bv0 = *(const float4*)bsrc;
        float4 bv1 = *(const float4*)(bsrc + 4);
        float4 bv2 = *(const float4*)(bsrc + 8);
        float4 bv3 = *(const float4*)(bsrc + 12);
        __syncthreads();
        *(float4*)&As[ar * AS_STRIDE + ak]      = av0;
        *(float4*)&As[ar * AS_STRIDE + ak + 4]  = av1;
        *(float4*)&As[ar * AS_STRIDE + ak + 8]  = av2;
        *(float4*)&As[ar * AS_STRIDE + ak + 12] = av3;
        *(float4*)&Bs[br * BS_STRIDE + bn16]      = bv0;
        *(float4*)&Bs[br * BS_STRIDE + bn16 + 4]  = bv1;
        *(float4*)&Bs[br * BS_STRIDE + bn16 + 8]  = bv2;
        *(float4*)&Bs[br * BS_STRIDE + bn16 + 12] = bv3;
        __syncthreads();

        #pragma unroll
        for (int ks = 0; ks < 4; ks++) {
            const int col = ks * 8 + (lane & 3);
            uint32_t ah[2][4], al[2][4];
            #pragma unroll
            for (int ms = 0; ms < 2; ms++) {
                int mb = wm * 32 + ms * 16 + (lane >> 2);
                float x0 = As[mb * AS_STRIDE + col];
                float x1 = As[(mb + 8) * AS_STRIDE + col];
                float x2 = As[mb * AS_STRIDE + col + 4];
                float x3 = As[(mb + 8) * AS_STRIDE + col + 4];
                cvt_hilo(x0, ah[ms][0], al[ms][0]);
                cvt_hilo(x1, ah[ms][1], al[ms][1]);
                cvt_hilo(x2, ah[ms][2], al[ms][2]);
                cvt_hilo(x3, ah[ms][3], al[ms][3]);
            }
            const int row = ks * 8 + (lane & 3);
            #pragma unroll
            for (int nt = 0; nt < 8; nt++) {
                int nb = wn * 64 + nt * 8 + (lane >> 2);
                float y0 = Bs[row * BS_STRIDE + nb];
                float y1 = Bs[(row + 4) * BS_STRIDE + nb];
                uint32_t bh[2], bl[2];
                cvt_hilo(y0, bh[0], bl[0]);
                cvt_hilo(y1, bh[1], bl[1]);
                #pragma unroll
                for (int ms = 0; ms < 2; ms++) {
                    mma_tf32(acc[ms][nt], ah[ms], bh);
                    mma_tf32(acc[ms][nt], ah[ms], bl);
                    mma_tf32(acc[ms][nt], al[ms], bh);
                }
            }
        }
    }

    const float rsc = rsqrtf(1.f + BEPS);
    #pragma unroll
    for (int ms = 0; ms < 2; ms++)
        #pragma unroll
        for (int nt = 0; nt < 8; nt++) {
            int row0 = bm + wm * 32 + ms * 16 + (lane >> 2);
            int col0 = bn + wn * 64 + nt * 8 + 2 * (lane & 3);
            int c0 = col0 & 255, c1 = (col0 + 1) & 255;
            float s0 = gup[c0] * rsc, s1 = gup[c1] * rsc;
            float bi0 = bup[c0] * s0 + btup[c0];
            float bi1 = bup[c1] * s1 + btup[c1];
            *(float2*)&up2_g[(size_t)row0 * 6400 + col0] =
                make_float2(fmaxf(acc[ms][nt][0] * s0 + bi0, 0.f),
                            fmaxf(acc[ms][nt][1] * s1 + bi1, 0.f));
            *(float2*)&up2_g[(size_t)(row0 + 8) * 6400 + col0] =
                make_float2(fmaxf(acc[ms][nt][2] * s0 + bi0, 0.f),
                            fmaxf(acc[ms][nt][3] * s1 + bi1, 0.f));
        }
}

// g GEMM: G[102400 x 144] = up2[102400 x 256] * wd1[256 x 144]
// 512 threads: 16 warps = 8 m-warps (16 rows) x 2 n-warps (72 cols).
#define GBS_STRIDE 152
__global__ __launch_bounds__(512, 1) void g_gemm_kernel(const float* __restrict__ wd1)
{
    __shared__ float As[128 * AS_STRIDE];
    __shared__ float Bs[32 * GBS_STRIDE];

    const int t = threadIdx.x;
    const int lane = t & 31, wid = t >> 5;
    const int wm = wid & 7, wn = wid >> 3;
    const int bm = blockIdx.x * 128;

    float acc[9][4];
    #pragma unroll
    for (int j = 0; j < 9; j++)
        #pragma unroll
        for (int k = 0; k < 4; k++) acc[j][k] = 0.f;

    const int ar = t >> 2, ak = (t & 3) * 8;

    for (int k0 = 0; k0 < 256; k0 += 32) {
        const float* asrc = &up2_g[(size_t)(bm + ar) * 256 + k0 + ak];
        float4 av0 = *(const float4*)asrc;
        float4 av1 = *(const float4*)(asrc + 4);
        float bvals[9];
        #pragma unroll
        for (int j = 0; j < 9; j++) {
            int i = t + j * 512;
            int row = i / 144, col = i - row * 144;
            bvals[j] = wd1[(size_t)(k0 + row) * 144 + col];
        }
        __syncthreads();
        *(float4*)&As[ar * AS_STRIDE + ak]     = av0;
        *(float4*)&As[ar * AS_STRIDE + ak + 4] = av1;
        #pragma unroll
        for (int j = 0; j < 9; j++) {
            int i = t + j * 512;
            int row = i / 144, col = i - row * 144;
            Bs[row * GBS_STRIDE + col] = bvals[j];
        }
        __syncthreads();

        #pragma unroll
        for (int ks = 0; ks < 4; ks++) {
            const int col = ks * 8 + (lane & 3);
            uint32_t ah[4], al[4];
            {
                int mb = wm * 16 + (lane >> 2);
                float x0 = As[mb * AS_STRIDE + col];
                float x1 = As[(mb + 8) * AS_STRIDE + col];
                float x2 = As[mb * AS_STRIDE + col + 4];
                float x3 = As[(mb + 8) * AS_STRIDE + col + 4];
                cvt_hilo(x0, ah[0], al[0]);
                cvt_hilo(x1, ah[1], al[1]);
                cvt_hilo(x2, ah[2], al[2]);
                cvt_hilo(x3, ah[3], al[3]);
            }
            const int row = ks * 8 + (lane & 3);
            #pragma unroll
            for (int nt = 0; nt < 9; nt++) {
                int nb = wn * 72 + nt * 8 + (lane >> 2);
                float y0 = Bs[row * GBS_STRIDE + nb];
                float y1 = Bs[(row + 4) * GBS_STRIDE + nb];
                uint32_t bh[2], bl[2];
                cvt_hilo(y0, bh[0], bl[0]);
                cvt_hilo(y1, bh[1], bl[1]);
                mma_tf32(acc[nt], ah, bh);
                mma_tf32(acc[nt], ah, bl);
                mma_tf32(acc[nt], al, bh);
            }
        }
    }

    #pragma unroll
    for (int nt = 0; nt < 9; nt++) {
        int row0 = bm + wm * 16 + (lane >> 2);
        int col0 = wn * 72 + nt * 8 + 2 * (lane & 3);
        *(float2*)&G_g[(size_t)row0 * 144 + col0] = make_float2(acc[nt][0], acc[nt][1]);
        *(float2*)&G_g[(size_t)(row0 + 8) * 144 + col0] = make_float2(acc[nt][2], acc[nt][3]);
    }
}

// ---------------------------------------------------------------------------
// minsoftmax: distances from xp, min over pos, softmax -> w_g, minD out.
// ---------------------------------------------------------------------------
__global__ __launch_bounds__(512) void minsoftmax_kernel(float* __restrict__ out_minD)
{
    __shared__ float x2s[25];
    __shared__ float red[32];

    const int b = blockIdx.x;
    const int t = threadIdx.x;
    const int lane = t & 31, wid = t >> 5;

    for (int pos = wid; pos < 25; pos += 16) {
        const float* row = &h3T_g[((size_t)b * 25 + pos) * 256];
        float s = 0.f;
        #pragma unroll
        for (int j = 0; j < 8; j++) {
            float v = row[lane + 32 * j];
            s += v * v;
        }
        #pragma unroll
        for (int off = 16; off; off >>= 1) s += __shfl_xor_sync(0xffffffffu, s, off);
        if (!lane) x2s[pos] = s;
    }
    __syncthreads();

    const float pp = pp_g[t];
    float m = 3.0e38f;
    #pragma unroll 5
    for (int pos = 0; pos < 25; pos++) {
        float xv = xp_g[((size_t)b * 25 + pos) * 512 + t];
        float d = fmaxf(x2s[pos] - 2.f * xv + pp, 0.f);
        m = fminf(m, d);
    }
    out_minD[(size_t)b * 512 + t] = m;

    float a = -m;
    float v = a;
    #pragma unroll
    for (int off = 16; off; off >>= 1) v = fmaxf(v, __shfl_xor_sync(0xffffffffu, v, off));
    if (!lane) red[wid] = v;
    __syncthreads();
    if (t == 0) {
        float r = red[0];
        for (int i = 1; i < 16; i++) r = fmaxf(r, red[i]);
        red[16] = r;
    }
    __syncthreads();
    float amax = red[16];
    float e = expf(a - amax);
    float sv = e;
    #pragma unroll
    for (int off = 16; off; off >>= 1) sv += __shfl_xor_sync(0xffffffffu, sv, off);
    __syncthreads();
    if (!lane) red[wid] = sv;
    __syncthreads();
    if (t == 0) {
        float r = 0.f;
        for (int i = 0; i < 16; i++) r += red[i];
        red[16] = r;
    }
    __syncthreads();
    w_g[(size_t)b * 512 + t] = e * (1.f / red[16]);
}

// ---------------------------------------------------------------------------
// z GEMM (FFMA f32x2): z[4096x256] = w[4096x512] * proto[512x256]
// ---------------------------------------------------------------------------
__global__ __launch_bounds__(256) void z_gemm_kernel(const float* __restrict__ proto)
{
    __shared__ __align__(16) float As2[16][128];
    __shared__ __align__(16) float Bs2[16][64];
    const int bn = blockIdx.x * 64;
    const int bm = blockIdx.y * 128;
    const int t = threadIdx.x;
    const int tx = t & 15, ty = t >> 4;

    unsigned long long acc[4][4];
    #pragma unroll
    for (int i = 0; i < 4; i++)
        #pragma unroll
        for (int j = 0; j < 4; j++) acc[i][j] = 0ull;

    for (int k0 = 0; k0 < 512; k0 += 16) {
        #pragma unroll
        for (int s = t; s < 512; s += 256) {
            int r = s >> 2, kq = (s & 3) << 2;
            float4 v = *(const float4*)&w_g[(size_t)(bm + r) * 512 + k0 + kq];
            As2[kq + 0][r] = v.x; As2[kq + 1][r] = v.y;
            As2[kq + 2][r] = v.z; As2[kq + 3][r] = v.w;
        }
        {
            int kk = t >> 4, n4 = (t & 15) << 2;
            *(float4*)&Bs2[kk][n4] = *(const float4*)&proto[(size_t)(k0 + kk) * 256 + bn + n4];
        }
        __syncthreads();
        #pragma unroll
        for (int kk = 0; kk < 16; kk++) {
            ulonglong2 a01 = *(const ulonglong2*)&As2[kk][ty * 8];
            ulonglong2 a23 = *(const ulonglong2*)&As2[kk][ty * 8 + 4];
            float4 bv = *(const float4*)&Bs2[kk][tx * 4];
            unsigned long long bd0 = pack2(bv.x, bv.x), bd1 = pack2(bv.y, bv.y);
            unsigned long long bd2 = pack2(bv.z, bv.z), bd3 = pack2(bv.w, bv.w);
            acc[0][0] = ffma2(a01.x, bd0, acc[0][0]); acc[0][1] = ffma2(a01.x, bd1, acc[0][1]);
            acc[0][2] = ffma2(a01.x, bd2, acc[0][2]); acc[0][3] = ffma2(a01.x, bd3, acc[0][3]);
            acc[1][0] = ffma2(a01.y, bd0, acc[1][0]); acc[1][1] = ffma2(a01.y, bd1, acc[1][1]);
            acc[1][2] = ffma2(a01.y, bd2, acc[1][2]); acc[1][3] = ffma2(a01.y, bd3, acc[1][3]);
            acc[2][0] = ffma2(a23.x, bd0, acc[2][0]); acc[2][1] = ffma2(a23.x, bd1, acc[2][1]);
            acc[2][2] = ffma2(a23.x, bd2, acc[2][2]); acc[2][3] = ffma2(a23.x, bd3, acc[2][3]);
            acc[3][0] = ffma2(a23.y, bd0, acc[3][0]); acc[3][1] = ffma2(a23.y, bd1, acc[3][1]);
            acc[3][2] = ffma2(a23.y, bd2, acc[3][2]); acc[3][3] = ffma2(a23.y, bd3, acc[3][3]);
        }
        __syncthreads();
    }

    #pragma unroll
    for (int mp = 0; mp < 4; mp++) {
        int m0 = bm + ty * 8 + mp * 2;
        float2 f0 = unpack2(acc[mp][0]), f1 = unpack2(acc[mp][1]);
        float2 f2 = unpack2(acc[mp][2]), f3 = unpack2(acc[mp][3]);
        float4 r0 = make_float4(f0.x, f1.x, f2.x, f3.x);
        float4 r1 = make_float4(f0.y, f1.y, f2.y, f3.y);
        *(float4*)&z_g[(size_t)m0 * 256 + bn + tx * 4] = r0;
        *(float4*)&z_g[(size_t)(m0 + 1) * 256 + bn + tx * 4] = r1;
    }
}

// ---------------------------------------------------------------------------
// dec2: d1 = scatter(G)+BN+relu, then d2, d3. 2 images per block, 256 threads.
// ---------------------------------------------------------------------------
__global__ __launch_bounds__(256) void dec2_kernel(
    const float* __restrict__ bd1,
    const float* __restrict__ gd1, const float* __restrict__ btd1,
    const float* __restrict__ wd2, const float* __restrict__ bd2,
    const float* __restrict__ gd2, const float* __restrict__ btd2,
    const float* __restrict__ wd3, const float* __restrict__ bd3,
    float* __restrict__ out)
{
    extern __shared__ float sm[];
    float* Gs   = sm;                 // 2 * 3600
    float* d1s  = Gs + 7200;          // 2 * 784
    float* d2s  = d1s + 1568;         // 2 * 1568
    float* wd2s = d2s + 3136;         // 1152
    float* wd3s = wd2s + 1152;        // 72

    const int t = threadIdx.x;
    const int b0 = blockIdx.x * 2;
    const float rs = rsqrtf(1.f + BEPS);

    for (int i = t; i < 7200; i += 256) Gs[i] = G_g[(size_t)b0 * 3600 + i];
    for (int i = t; i < 1152; i += 256) wd2s[i] = wd2[i];
    if (t < 72) wd3s[t] = wd3[t];
    __syncthreads();

    // ---- d1: scatter-sum of G + BN + relu. 2*16*49 = 1568 outputs.
    for (int idx = t; idx < 1568; idx += 256) {
        int img = idx / 784, r = idx - img * 784;
        int o = r / 49, pos = r - o * 49;
        int oi = pos / 7, oj = pos % 7;
        int y0 = max(oi - 2, 0), y1 = min(oi, 4);
        int x0 = max(oj - 2, 0), x1 = min(oj, 4);
        float sum = 0.f;
        const float* Gb = &Gs[img * 3600];
        for (int y = y0; y <= y1; y++) {
            int ki = oi - y;
            for (int xx = x0; xx <= x1; xx++) {
                int kj = oj - xx;
                sum += Gb[(y * 5 + xx) * 144 + o * 9 + ki * 3 + kj];
            }
        }
        float s = gd1[o] * rs;
        d1s[img * 784 + o * 49 + pos] = fmaxf((sum + bd1[o]) * s + btd1[o], 0.f);
    }
    __syncthreads();

    // ---- d2: conv_t 16->8, k3 s2 p1 op1, 7->14. 196 threads, 2 imgs x 8 oc.
    if (t < 196) {
        float acc2[2][8];
        #pragma unroll
        for (int a = 0; a < 2; a++)
            #pragma unroll
            for (int o = 0; o < 8; o++) acc2[a][o] = 0.f;
        int i = t / 14, j = t % 14;
        int ylo = i / 2, yhi = min((i + 1) / 2, 6);
        int xlo = j / 2, xhi = min((j + 1) / 2, 6);
        for (int c = 0; c < 16; c++) {
            for (int y = ylo; y <= yhi; y++) {
                int ki = i - 2 * y + 1;
                for (int xx = xlo; xx <= xhi; xx++) {
                    int kj = j - 2 * xx + 1;
                    float u0 = d1s[0 * 784 + c * 49 + y * 7 + xx];
                    float u1 = d1s[1 * 784 + c * 49 + y * 7 + xx];
                    #pragma unroll
                    for (int o = 0; o < 8; o++) {
                        float wv = wd2s[((c * 8 + o) * 3 + ki) * 3 + kj];
                        acc2[0][o] += u0 * wv;
                        acc2[1][o] += u1 * wv;
                    }
                }
            }
        }
        #pragma unroll
        for (int o = 0; o < 8; o++) {
            float s = gd2[o] * rs;
            float bias = bd2[o] * s + btd2[o];
            #pragma unroll
            for (int a = 0; a < 2; a++)
                d2s[a * 1568 + o * 196 + t] = fmaxf(acc2[a][o] * s + bias, 0.f);
        }
    }
    __syncthreads();

    // ---- d3: conv_t 8->1, k3 s2 p1 op1, 14->28, sigmoid
    const float bb3 = bd3[0];
    for (int idx = t; idx < 1568; idx += 256) {
        int a = idx / 784, p = idx - a * 784, i = p / 28, j = p % 28;
        int ylo = i / 2, yhi = min((i + 1) / 2, 13);
        int xlo = j / 2, xhi = min((j + 1) / 2, 13);
        float acc3 = bb3;
        for (int c = 0; c < 8; c++) {
            for (int y = ylo; y <= yhi; y++) {
                int ki = i - 2 * y + 1;
                for (int xx = xlo; xx <= xhi; xx++) {
                    int kj = j - 2 * xx + 1;
                    acc3 += d2s[a * 1568 + c * 196 + y * 14 + xx] * wd3s[c * 9 + ki * 3 + kj];
                }
            }
        }
        out[(size_t)(b0 + a) * 784 + p] = 1.f / (1.f + expf(-acc3));
    }
}

// ---------------------------------------------------------------------------
extern "C" void kernel_launch(void* const* d_in, const int* in_sizes, int n_in,
                              void* d_out, int out_size)
{
    const float* x     = (const float*)d_in[0];
    const float* w1    = (const float*)d_in[1];
    const float* b1    = (const float*)d_in[2];
    const float* w2    = (const float*)d_in[3];
    const float* b2    = (const float*)d_in[4];
    const float* g2    = (const float*)d_in[5];
    const float* bt2   = (const float*)d_in[6];
    const float* w3    = (const float*)d_in[7];
    const float* b3    = (const float*)d_in[8];
    const float* proto = (const float*)d_in[9];
    const float* wup   = (const float*)d_in[10];
    const float* bup   = (const float*)d_in[11];
    const float* gup   = (const float*)d_in[12];
    const float* btup  = (const float*)d_in[13];
    const float* wd1   = (const float*)d_in[14];
    const float* bd1   = (const float*)d_in[15];
    const float* gd1   = (const float*)d_in[16];
    const float* btd1  = (const float*)d_in[17];
    const float* wd2   = (const float*)d_in[18];
    const float* bd2   = (const float*)d_in[19];
    const float* gd2   = (const float*)d_in[20];
    const float* btd2  = (const float*)d_in[21];
    const float* wd3   = (const float*)d_in[22];
    const float* bd3   = (const float*)d_in[23];

    float* out  = (float*)d_out;                 // (4096,1,28,28)
    float* minD = out + (size_t)NB * 784;        // (4096,512)

    prep_kernel<<<256, 256>>>(proto, w3, wup);
    enc12_kernel<<<NB, 128>>>(x, w1, b1, w2, b2, g2, bt2);
    conv3_kernel<<<NB, 256>>>(b3);

    dim3 gx(512 / 128, (NB * 25) / 128);         // (4, 800)
    xp_gemm_kernel<<<gx, 256>>>();

    minsoftmax_kernel<<<NB, 512>>>(minD);

    dim3 gz(256 / 64, NB / 128);
    z_gemm_kernel<<<gz, 256>>>(proto);

    dim3 gu(6400 / 128, NB / 128);               // (50, 32)
    up_gemm_kernel<<<gu, 256>>>(bup, gup, btup);

    g_gemm_kernel<<<(NB * 25) / 128, 512>>>(wd1);   // 800 blocks

    size_t smem2 = (size_t)(7200 + 1568 + 3136 + 1152 + 72) * sizeof(float); // 52,512 B
    cudaFuncSetAttribute(dec2_kernel, cudaFuncAttributeMaxDynamicSharedMemorySize, (int)smem2);
    dec2_kernel<<<NB / 2, 256, smem2>>>(bd1, gd1, btd1,
                                        wd2, bd2, gd2, btd2,
                                        wd3, bd3, out);
}